// round 14
// baseline (speedup 1.0000x reference)
#include <cuda_runtime.h>
#include <cuda_bf16.h>
#include <math.h>
#include <stdint.h>

#define NB 4
#define NH 8
#define SEGL 1024
#define TOT 2048
#define DD 128

// ---------------- scratch (device globals; no allocations) ----------------
__device__ float g_pos[TOT*DD];           // sinusoid table
__device__ __nv_bfloat16 g_qh[NB*NH*SEGL*DD];
__device__ __nv_bfloat16 g_ql[NB*NH*SEGL*DD];
__device__ __nv_bfloat16 g_kh[NB*NH*TOT*DD];
__device__ __nv_bfloat16 g_kl[NB*NH*TOT*DD];
__device__ __nv_bfloat16 g_vh[NB*NH*TOT*DD];   // V single bf16 plane
__device__ __nv_bfloat16 g_rh[NH*TOT*DD];
__device__ __nv_bfloat16 g_rl[NH*TOT*DD];
__device__ float g_u1k[NB*NH*TOT];
__device__ float g_u2r[NH*TOT];
__device__ float g_att[NB*SEGL*NH*DD];
__device__ __nv_bfloat16 g_G[(size_t)NB*NH*SEGL*TOT + 4096]; // +pad for aligned over-fetch

// ---------------- helpers ----------------
__device__ __forceinline__ uint32_t smem_u32(const void* p) {
    uint32_t a;
    asm("{ .reg .u64 t; cvta.to.shared.u64 t, %1; cvt.u32.u64 %0, t; }" : "=r"(a) : "l"(p));
    return a;
}
__device__ __forceinline__ uint32_t pack_bf16x2(float lo, float hi) {
    uint32_t d; asm("cvt.rn.bf16x2.f32 %0, %1, %2;" : "=r"(d) : "f"(hi), "f"(lo)); return d;
}
__device__ __forceinline__ void cp16(uint32_t dst, const void* src) {
    asm volatile("cp.async.cg.shared.global [%0], [%1], 16;" :: "r"(dst), "l"(src) : "memory");
}
#define CP_COMMIT() asm volatile("cp.async.commit_group;" ::: "memory")
#define CP_WAIT(n)  asm volatile("cp.async.wait_group %0;" :: "n"(n) : "memory")

#define LDSM_X4(r, addr) \
    asm volatile("ldmatrix.sync.aligned.m8n8.x4.shared.b16 {%0,%1,%2,%3}, [%4];" \
        : "=r"((r)[0]), "=r"((r)[1]), "=r"((r)[2]), "=r"((r)[3]) : "r"(addr))
#define LDSM_X4_T(r, addr) \
    asm volatile("ldmatrix.sync.aligned.m8n8.x4.trans.shared.b16 {%0,%1,%2,%3}, [%4];" \
        : "=r"((r)[0]), "=r"((r)[1]), "=r"((r)[2]), "=r"((r)[3]) : "r"(addr))
#define MMA_BF16(c, a, b) \
    asm volatile("mma.sync.aligned.m16n8k16.row.col.f32.bf16.bf16.f32 " \
        "{%0,%1,%2,%3}, {%4,%5,%6,%7}, {%8,%9}, {%0,%1,%2,%3};" \
        : "+f"((c)[0]), "+f"((c)[1]), "+f"((c)[2]), "+f"((c)[3]) \
        : "r"((a)[0]), "r"((a)[1]), "r"((a)[2]), "r"((a)[3]), "r"((b)[0]), "r"((b)[1]))

__device__ __forceinline__ void split4_bf16(float4 v, ushort4& hv, ushort4& lv) {
    __nv_bfloat16 b;
    b = __float2bfloat16(v.x); hv.x = __bfloat16_as_ushort(b);
    lv.x = __bfloat16_as_ushort(__float2bfloat16(v.x - __bfloat162float(b)));
    b = __float2bfloat16(v.y); hv.y = __bfloat16_as_ushort(b);
    lv.y = __bfloat16_as_ushort(__float2bfloat16(v.y - __bfloat162float(b)));
    b = __float2bfloat16(v.z); hv.z = __bfloat16_as_ushort(b);
    lv.z = __bfloat16_as_ushort(__float2bfloat16(v.z - __bfloat162float(b)));
    b = __float2bfloat16(v.w); hv.w = __bfloat16_as_ushort(b);
    lv.w = __bfloat16_as_ushort(__float2bfloat16(v.w - __bfloat162float(b)));
}
__device__ __forceinline__ void split2_bf16(float a, float b, ushort2& hv, ushort2& lv) {
    __nv_bfloat16 t;
    t = __float2bfloat16(a); hv.x = __bfloat16_as_ushort(t);
    lv.x = __bfloat16_as_ushort(__float2bfloat16(a - __bfloat162float(t)));
    t = __float2bfloat16(b); hv.y = __bfloat16_as_ushort(t);
    lv.y = __bfloat16_as_ushort(__float2bfloat16(b - __bfloat162float(t)));
}

// ---------------- sinusoid position table ----------------
__global__ __launch_bounds__(256) void pos_kernel()
{
    int idx = blockIdx.x * 256 + threadIdx.x;
    int m = idx >> 7, e = idx & 127;
    float pp = (float)(2047 - m);
    float ang = pp / powf(10000.0f, (float)(2 * e) * (1.0f / 128.0f));
    g_pos[idx] = ((e & 1) == 0) ? sinf(ang) : cosf(ang);
}

// ---------------- projection GEMMs: 64m x 64n tiles (R13-proven) ----------------
template<int MODE>
__global__ __launch_bounds__(256, 3) void proj_mma_kernel(const float* __restrict__ X,
                                                          const float* __restrict__ MEMI,
                                                          const float* __restrict__ W, int N)
{
    extern __shared__ __align__(16) unsigned short sm16[];
    unsigned short* Ah = sm16;              // 64*136
    unsigned short* Al = Ah + 64 * 136;
    unsigned short* Bh = Al + 64 * 136;     // 128*72 ([k][n])
    unsigned short* Bl = Bh + 128 * 72;

    const int m0 = blockIdx.y * 64;
    const int n0 = blockIdx.x * 64;
    const int tid = threadIdx.x, wid = tid >> 5, lane = tid & 31;

    #pragma unroll
    for (int i = 0; i < 8; i++) {
        int f = tid + i * 256;
        int row = f >> 5, col = (f & 31) << 2;
        int m = m0 + row;
        float4 a;
        if (MODE == 0) {
            a = *(const float4*)(X + (size_t)m * 128 + col);
        } else if (MODE == 1) {
            int bb = m >> 11, sp = m & 2047;
            const float* src = (sp < 1024) ? (MEMI + ((size_t)bb * 1024 + sp) * 128)
                                           : (X    + ((size_t)bb * 1024 + sp - 1024) * 128);
            a = *(const float4*)(src + col);
        } else {
            a = *(const float4*)(g_pos + (size_t)m * 128 + col);
        }
        ushort4 hv, lv;
        split4_bf16(a, hv, lv);
        *(ushort4*)(Ah + row * 136 + col) = hv;
        *(ushort4*)(Al + row * 136 + col) = lv;
    }
    #pragma unroll
    for (int i = 0; i < 8; i++) {
        int f = tid + i * 256;
        int row = f >> 4, col = (f & 15) << 2;
        float4 w = *(const float4*)(W + (size_t)row * N + n0 + col);
        ushort4 hv, lv;
        split4_bf16(w, hv, lv);
        *(ushort4*)(Bh + row * 72 + col) = hv;
        *(ushort4*)(Bl + row * 72 + col) = lv;
    }
    __syncthreads();

    const int wm = (wid >> 1) * 16;
    const int wn = (wid & 1) * 32;
    const int arow = (lane & 7) + ((lane >> 3) & 1) * 8;
    const int akoff = (lane >> 4) * 16;
    const int vtrow = ((lane >> 3) & 1) * 8 + (lane & 7);
    const int vncol = ((lane >> 4) & 1) * 8;

    const uint32_t ah_b = smem_u32(Ah), al_b = smem_u32(Al);
    const uint32_t bh_b = smem_u32(Bh), bl_b = smem_u32(Bl);

    float cs[4][4];
    #pragma unroll
    for (int nt = 0; nt < 4; nt++)
        #pragma unroll
        for (int e = 0; e < 4; e++) cs[nt][e] = 0.f;

    #pragma unroll
    for (int ks = 0; ks < 8; ks++) {
        uint32_t ah[4], al4[4];
        uint32_t offA = (uint32_t)((wm + arow) * 272 + ks * 32 + akoff);
        LDSM_X4(ah, ah_b + offA);
        LDSM_X4(al4, al_b + offA);
        #pragma unroll
        for (int np = 0; np < 2; np++) {
            uint32_t bh4[4], bl4[4];
            uint32_t offB = (uint32_t)((ks * 16 + vtrow) * 144 + (wn + np * 16 + vncol) * 2);
            LDSM_X4_T(bh4, bh_b + offB);
            LDSM_X4_T(bl4, bl_b + offB);
            MMA_BF16(cs[2 * np],     ah,  &bh4[0]);
            MMA_BF16(cs[2 * np],     ah,  &bl4[0]);
            MMA_BF16(cs[2 * np],     al4, &bh4[0]);
            MMA_BF16(cs[2 * np + 1], ah,  &bh4[2]);
            MMA_BF16(cs[2 * np + 1], ah,  &bl4[2]);
            MMA_BF16(cs[2 * np + 1], al4, &bh4[2]);
        }
    }

    const int gp = lane >> 2, tg = lane & 3;
    #pragma unroll
    for (int half = 0; half < 2; half++) {
        int m = m0 + wm + gp + 8 * half;
        #pragma unroll
        for (int nt = 0; nt < 4; nt++) {
            int col = wn + nt * 8 + 2 * tg;
            int fp = n0 + col;
            float v0 = cs[nt][2 * half], v1 = cs[nt][2 * half + 1];
            if (MODE == 0) {
                int b_ = m >> 10, sp = m & 1023;
                int h = sp >> 7;
                int s = ((sp & 127) << 3) + (fp >> 7);
                int e = fp & 127;
                size_t off = ((((size_t)b_ * 8 + h) * 1024 + s) << 7) + e;
                ushort2 hv, lv;
                split2_bf16(v0, v1, hv, lv);
                *(ushort2*)(g_qh + off) = hv;
                *(ushort2*)(g_ql + off) = lv;
            } else if (MODE == 1) {
                int bb = m >> 11, sp = m & 2047;
                int cc = bb * 2 + (sp >> 10);
                int h = (sp & 1023) >> 7;
                int t = ((sp & 127) << 4) + (fp >> 7);
                int e = fp & 127;
                if (cc < 4) {
                    size_t off = ((((size_t)cc * 8 + h) * 2048 + t) << 7) + e;
                    ushort2 hv, lv;
                    split2_bf16(v0, v1, hv, lv);
                    *(ushort2*)(g_kh + off) = hv;
                    *(ushort2*)(g_kl + off) = lv;
                } else {
                    size_t off = ((((size_t)(cc - 4) * 8 + h) * 2048 + t) << 7) + e;
                    ushort2 hv;
                    hv.x = __bfloat16_as_ushort(__float2bfloat16(v0));
                    hv.y = __bfloat16_as_ushort(__float2bfloat16(v1));
                    *(ushort2*)(g_vh + off) = hv;
                }
            } else {
                int h = m >> 8;
                int t = ((m & 255) << 3) + (fp >> 7);
                int e = fp & 127;
                size_t off = (((size_t)h * 2048 + t) << 7) + e;
                ushort2 hv, lv;
                split2_bf16(v0, v1, hv, lv);
                *(ushort2*)(g_rh + off) = hv;
                *(ushort2*)(g_rl + off) = lv;
            }
        }
    }
}

// ---------------- u1·k and u2·r from bf16 hi/lo planes ----------------
__global__ __launch_bounds__(256) void udot_kernel(const float* __restrict__ U, int which, int nrows)
{
    int row = blockIdx.x * 8 + (threadIdx.x >> 5);
    int lane = threadIdx.x & 31;
    if (row >= nrows) return;
    const __nv_bfloat16* Mh = which ? g_rh : g_kh;
    const __nv_bfloat16* Ml = which ? g_rl : g_kl;
    float* Out = which ? g_u2r : g_u1k;
    int h = (row >> 11) & 7;
    float4 u = *(const float4*)(U + h * 128 + lane * 4);
    ushort4 mh = *(const ushort4*)(Mh + (size_t)row * 128 + lane * 4);
    ushort4 ml = *(const ushort4*)(Ml + (size_t)row * 128 + lane * 4);
    float m0 = __bfloat162float(__ushort_as_bfloat16(mh.x)) + __bfloat162float(__ushort_as_bfloat16(ml.x));
    float m1 = __bfloat162float(__ushort_as_bfloat16(mh.y)) + __bfloat162float(__ushort_as_bfloat16(ml.y));
    float m2 = __bfloat162float(__ushort_as_bfloat16(mh.z)) + __bfloat162float(__ushort_as_bfloat16(ml.z));
    float m3 = __bfloat162float(__ushort_as_bfloat16(mh.w)) + __bfloat162float(__ushort_as_bfloat16(ml.w));
    float s = u.x * m0 + u.y * m1 + u.z * m2 + u.w * m3;
    #pragma unroll
    for (int o = 16; o; o >>= 1) s += __shfl_xor_sync(0xffffffffu, s, o);
    if (lane == 0) Out[row] = s;
}

// ---------------- banded G = qh.(rh+rl) via bf16 mma.sync (2-term; storage-limited) ----------------
__global__ __launch_bounds__(256, 2) void ggemm_mma_kernel()
{
    extern __shared__ __align__(16) unsigned short sm16[];
    unsigned short* Qh = sm16;              // 128*136
    unsigned short* Rh = Qh + 128 * 136;    // 64*136
    unsigned short* Rl = Rh + 64 * 136;

    const int rt = blockIdx.x, st = blockIdx.y, bh = blockIdx.z;
    if (rt < 14 - 2 * st) return;
    const int h = bh & 7;
    const int s0 = st * 128, r0 = rt * 64;
    const int tid = threadIdx.x, wid = tid >> 5, lane = tid & 31;

    const unsigned short* qh = (const unsigned short*)g_qh + ((size_t)bh * 1024 + s0) * 128;
    #pragma unroll
    for (int i = 0; i < 8; i++) {
        int f = tid + i * 256;
        int row = f >> 4, c8 = (f & 15) << 3;
        *(uint4*)(Qh + row * 136 + c8) = *(const uint4*)(qh + (size_t)row * 128 + c8);
    }
    const unsigned short* rh = (const unsigned short*)g_rh + ((size_t)h * 2048 + r0) * 128;
    const unsigned short* rl = (const unsigned short*)g_rl + ((size_t)h * 2048 + r0) * 128;
    #pragma unroll
    for (int i = 0; i < 4; i++) {
        int f = tid + i * 256;
        int row = f >> 4, c8 = (f & 15) << 3;
        *(uint4*)(Rh + row * 136 + c8) = *(const uint4*)(rh + (size_t)row * 128 + c8);
        *(uint4*)(Rl + row * 136 + c8) = *(const uint4*)(rl + (size_t)row * 128 + c8);
    }
    __syncthreads();

    const int wm = (wid >> 1) * 32;
    const int wn = (wid & 1) * 32;

    float c[2][4][4];
    #pragma unroll
    for (int mt = 0; mt < 2; mt++)
        #pragma unroll
        for (int nt = 0; nt < 4; nt++)
            #pragma unroll
            for (int e = 0; e < 4; e++) c[mt][nt][e] = 0.f;

    const int arow = (lane & 7) + ((lane >> 3) & 1) * 8;
    const int akoff = (lane >> 4) * 16;
    const int brow = lane & 7;
    const int bkoff = ((lane >> 3) & 1) * 16;

    const uint32_t qh_b = smem_u32(Qh);
    const uint32_t rh_b = smem_u32(Rh), rl_b = smem_u32(Rl);

    #pragma unroll
    for (int ks = 0; ks < 8; ks++) {
        uint32_t ah[2][4];
        #pragma unroll
        for (int mt = 0; mt < 2; mt++) {
            uint32_t off = (uint32_t)((wm + mt * 16 + arow) * 272 + ks * 32 + akoff);
            LDSM_X4(ah[mt], qh_b + off);
        }
        uint32_t bhf[4][2], blf[4][2];
        #pragma unroll
        for (int nt = 0; nt < 4; nt++) {
            uint32_t off = (uint32_t)((wn + nt * 8 + brow) * 272 + ks * 32 + bkoff);
            asm volatile("ldmatrix.sync.aligned.m8n8.x2.shared.b16 {%0,%1}, [%2];"
                : "=r"(bhf[nt][0]), "=r"(bhf[nt][1]) : "r"(rh_b + off));
            asm volatile("ldmatrix.sync.aligned.m8n8.x2.shared.b16 {%0,%1}, [%2];"
                : "=r"(blf[nt][0]), "=r"(blf[nt][1]) : "r"(rl_b + off));
        }
        #pragma unroll
        for (int mt = 0; mt < 2; mt++)
            #pragma unroll
            for (int nt = 0; nt < 4; nt++) {
                MMA_BF16(c[mt][nt], ah[mt], bhf[nt]);
                MMA_BF16(c[mt][nt], ah[mt], blf[nt]);
            }
    }

    const int gp = lane >> 2, tg = lane & 3;
    __nv_bfloat16* Gb = g_G + (size_t)bh * (1024 * 2048);
    #pragma unroll
    for (int mt = 0; mt < 2; mt++) {
        int mrow = s0 + wm + mt * 16 + gp;
        #pragma unroll
        for (int nt = 0; nt < 4; nt++) {
            int n = r0 + wn + nt * 8 + 2 * tg;
            *(uint32_t*)(Gb + (size_t)mrow * 2048 + n)       = pack_bf16x2(c[mt][nt][0], c[mt][nt][1]);
            *(uint32_t*)(Gb + (size_t)(mrow + 8) * 2048 + n) = pack_bf16x2(c[mt][nt][2], c[mt][nt][3]);
        }
    }
}

// ---------------- flash attention: 512 threads, warps split t, cp.async pipeline ----------------
__global__ __launch_bounds__(512, 1) void attn_kernel()
{
    extern __shared__ __align__(16) char smraw[];
    unsigned short* Qh  = (unsigned short*)smraw;     // 128*136
    unsigned short* Ql  = Qh + 128 * 136;
    unsigned short* Kh0 = Ql + 128 * 136;             // 2 bufs x 64*136
    unsigned short* Kl0 = Kh0 + 2 * 64 * 136;
    unsigned short* Vh0 = Kl0 + 2 * 64 * 136;
    unsigned short* Gs0 = Vh0 + 2 * 64 * 136;         // 2 bufs x 128*80
    float* biasF = (float*)(Gs0 + 2 * 128 * 80);      // 2 bufs x 128 floats
    float* red   = biasF + 2 * 128;                   // 128 x 4 (cross-warp max|sum)

    const int st = 7 - blockIdx.x;                    // heavy-first
    const int bh = blockIdx.y, h = bh & 7;
    const int s0 = st * 128;
    const int tid = threadIdx.x;
    const int wid = tid >> 5, lane = tid & 31;
    const int wm = (wid >> 1) * 16;                   // 8 row-groups
    const int wn = (wid & 1) * 32;                    // t-half within 64-tile
    const int gp = lane >> 2, tg = lane & 3;
    const int arow = (lane & 7) + ((lane >> 3) & 1) * 8;
    const int akoff = (lane >> 4) * 16;
    const int b4row = ((lane >> 4) & 1) * 8 + (lane & 7);
    const int b4koff = ((lane >> 3) & 1) * 16;
    const int vtrow = ((lane >> 3) & 1) * 8 + (lane & 7);
    const int vncol = ((lane >> 4) & 1) * 8;

    const unsigned short* qhp = (const unsigned short*)g_qh + ((size_t)bh * 1024 + s0) * 128;
    const unsigned short* qlp = (const unsigned short*)g_ql + ((size_t)bh * 1024 + s0) * 128;
    const unsigned short* khp = (const unsigned short*)g_kh + (size_t)bh * (2048 * 128);
    const unsigned short* klp = (const unsigned short*)g_kl + (size_t)bh * (2048 * 128);
    const unsigned short* vhp = (const unsigned short*)g_vh + (size_t)bh * (2048 * 128);
    const unsigned short* Gbh = (const unsigned short*)g_G + (size_t)bh * (1024 * 2048);

    // stage Q hi/lo once (512 threads: 4096 uint4 over both planes)
    #pragma unroll
    for (int i = 0; i < 4; i++) {
        int f = tid + i * 512;
        int pl = f >> 11;
        int rc = f & 2047;
        int row = rc >> 4, c8 = (rc & 15) << 3;
        unsigned short* dstp = pl ? Ql : Qh;
        const unsigned short* srcp = pl ? qlp : qhp;
        *(uint4*)(dstp + row * 136 + c8) = *(const uint4*)(srcp + (size_t)row * 128 + c8);
    }

    const uint32_t qh_b = smem_u32(Qh), ql_b = smem_u32(Ql);
    const uint32_t khBase = smem_u32(Kh0), klBase = smem_u32(Kl0), vhBase = smem_u32(Vh0);
    const uint32_t gsBase = smem_u32(Gs0), biasBase = smem_u32(biasF);

    auto stage = [&](int b, int tt) {
        const int t0 = tt * 64;
        const uint32_t kh = khBase + b * 17408;
        const uint32_t kl = klBase + b * 17408;
        const uint32_t vh = vhBase + b * 17408;
        const uint32_t gs = gsBase + b * 20480;
        const uint32_t bb = biasBase + b * 512;
        #pragma unroll
        for (int i = 0; i < 6; i++) {            // K hi/lo + V: 3072 chunks
            int idx = tid + i * 512;
            int p = idx >> 10;
            int rc = idx & 1023;
            int row = rc >> 4, ch = rc & 15;
            uint32_t dst = (p == 0 ? kh : p == 1 ? kl : vh) + (uint32_t)(row * 272 + ch * 16);
            const unsigned short* src = (p == 0 ? khp : p == 1 ? klp : vhp)
                                      + (size_t)(t0 + row) * 128 + ch * 8;
            cp16(dst, src);
        }
        const int relbase = t0 - s0 + 1023;
        #pragma unroll
        for (int i = 0; i < 3; i++) {            // G band: 1152 chunks
            int idx = tid + i * 512;
            if (idx < 1152) {
                int row = idx / 9, ch = idx - row * 9;
                int start = (relbase - row) & ~7;
                cp16(gs + (uint32_t)(row * 160 + ch * 16),
                     Gbh + (size_t)(s0 + row) * 2048 + start + ch * 8);
            }
        }
        if (tid < 32) {
            int arr = tid >> 4, c = tid & 15;
            const float* src = arr ? (g_u2r + (size_t)h * 2048 + t0 + c * 4)
                                   : (g_u1k + (size_t)bh * 2048 + t0 + c * 4);
            cp16(bb + (uint32_t)(arr * 256 + c * 16), src);
        }
    };

    float o[16][4];
    #pragma unroll
    for (int nt = 0; nt < 16; nt++)
        #pragma unroll
        for (int e = 0; e < 4; e++) o[nt][e] = 0.f;

    float mrow[2], lrow[2];
    mrow[0] = mrow[1] = -1e30f;
    lrow[0] = lrow[1] = 0.f;

    const float scale = 0.08838834764831843f; // 1/sqrt(128)
    const int r0 = wm + gp, r1 = r0 + 8;
    const int sg0 = s0 + r0, sg1 = s0 + r1;
    const int slot = wid & 1;

    const int ntiles = 2 * st + 18;
    stage(0, 0);
    CP_COMMIT();
    int buf = 0;

    for (int tt = 0; tt < ntiles; tt++) {
        __syncthreads();
        if (tt + 1 < ntiles) {
            stage(buf ^ 1, tt + 1);
            CP_COMMIT();
            CP_WAIT(1);
        } else {
            CP_WAIT(0);
        }
        __syncthreads();

        const int t0 = tt * 64;
        const int relbase = t0 - s0 + 1023;
        const uint32_t kh_b = khBase + buf * 17408;
        const uint32_t kl_b = klBase + buf * 17408;
        const uint32_t vh_b = vhBase + buf * 17408;
        const unsigned short* GsB = Gs0 + buf * 10240;
        const float* bA = biasF + buf * 128;
        const int off0 = (relbase - r0) & 7;
        const int off1 = (relbase - r1) & 7;

        // ---- QK: warp owns rows [wm,wm+16), cols [wn,wn+32) ----
        float cs[4][4];
        #pragma unroll
        for (int nt = 0; nt < 4; nt++)
            #pragma unroll
            for (int e = 0; e < 4; e++) cs[nt][e] = 0.f;

        #pragma unroll
        for (int ks = 0; ks < 8; ks++) {
            uint32_t ah[4], al4[4];
            uint32_t offA = (uint32_t)((wm + arow) * 272 + ks * 32 + akoff);
            LDSM_X4(ah, qh_b + offA);
            LDSM_X4(al4, ql_b + offA);
            #pragma unroll
            for (int np = 0; np < 2; np++) {
                uint32_t bh4[4], bl4[4];
                uint32_t offB = (uint32_t)((wn + np * 16 + b4row) * 272 + ks * 32 + b4koff);
                LDSM_X4(bh4, kh_b + offB);
                LDSM_X4(bl4, kl_b + offB);
                MMA_BF16(cs[2 * np],     ah,  &bh4[0]);
                MMA_BF16(cs[2 * np],     ah,  &bl4[0]);
                MMA_BF16(cs[2 * np],     al4, &bh4[0]);
                MMA_BF16(cs[2 * np + 1], ah,  &bh4[2]);
                MMA_BF16(cs[2 * np + 1], ah,  &bl4[2]);
                MMA_BF16(cs[2 * np + 1], al4, &bh4[2]);
            }
        }

        // ---- bias + G + scale + mask ----
        float mx0 = -1e30f, mx1 = -1e30f;
        #pragma unroll
        for (int nt = 0; nt < 4; nt++) {
            int col = wn + nt * 8 + 2 * tg;
            int tgl = t0 + col;
            float b0 = bA[col] + bA[64 + col];
            float b1 = bA[col + 1] + bA[64 + col + 1];
            float g00 = __bfloat162float(*(const __nv_bfloat16*)(GsB + r0 * 80 + off0 + col));
            float g01 = __bfloat162float(*(const __nv_bfloat16*)(GsB + r0 * 80 + off0 + col + 1));
            float g10 = __bfloat162float(*(const __nv_bfloat16*)(GsB + r1 * 80 + off1 + col));
            float g11 = __bfloat162float(*(const __nv_bfloat16*)(GsB + r1 * 80 + off1 + col + 1));
            float v00 = (cs[nt][0] + g00 + b0) * scale;
            float v01 = (cs[nt][1] + g01 + b1) * scale;
            float v10 = (cs[nt][2] + g10 + b0) * scale;
            float v11 = (cs[nt][3] + g11 + b1) * scale;
            v00 = (tgl     - sg0 <= 1024) ? v00 : -1e30f;
            v01 = (tgl + 1 - sg0 <= 1024) ? v01 : -1e30f;
            v10 = (tgl     - sg1 <= 1024) ? v10 : -1e30f;
            v11 = (tgl + 1 - sg1 <= 1024) ? v11 : -1e30f;
            cs[nt][0] = v00; cs[nt][1] = v01; cs[nt][2] = v10; cs[nt][3] = v11;
            mx0 = fmaxf(mx0, fmaxf(v00, v01));
            mx1 = fmaxf(mx1, fmaxf(v10, v11));
        }
        mx0 = fmaxf(mx0, __shfl_xor_sync(0xffffffffu, mx0, 1));
        mx0 = fmaxf(mx0, __shfl_xor_sync(0xffffffffu, mx0, 2));
        mx1 = fmaxf(mx1, __shfl_xor_sync(0xffffffffu, mx1, 1));
        mx1 = fmaxf(mx1, __shfl_xor_sync(0xffffffffu, mx1, 2));

        // cross-warp max combine (partner owns other 32 cols)
        if (tg == 0) { red[r0 * 4 + slot] = mx0; red[r1 * 4 + slot] = mx1; }
        __syncthreads();
        mx0 = fmaxf(red[r0 * 4], red[r0 * 4 + 1]);
        mx1 = fmaxf(red[r1 * 4], red[r1 * 4 + 1]);

        float mn0 = fmaxf(mrow[0], mx0), mn1 = fmaxf(mrow[1], mx1);
        float al0 = __expf(mrow[0] - mn0), al1 = __expf(mrow[1] - mn1);
        float rs0 = 0.f, rs1 = 0.f;
        #pragma unroll
        for (int nt = 0; nt < 4; nt++) {
            float p00 = __expf(cs[nt][0] - mn0), p01 = __expf(cs[nt][1] - mn0);
            float p10 = __expf(cs[nt][2] - mn1), p11 = __expf(cs[nt][3] - mn1);
            rs0 += p00 + p01; rs1 += p10 + p11;
            cs[nt][0] = p00; cs[nt][1] = p01; cs[nt][2] = p10; cs[nt][3] = p11;
        }
        rs0 += __shfl_xor_sync(0xffffffffu, rs0, 1);
        rs0 += __shfl_xor_sync(0xffffffffu, rs0, 2);
        rs1 += __shfl_xor_sync(0xffffffffu, rs1, 1);
        rs1 += __shfl_xor_sync(0xffffffffu, rs1, 2);

        // cross-warp sum combine (slots 2,3; distinct from max slots)
        if (tg == 0) { red[r0 * 4 + 2 + slot] = rs0; red[r1 * 4 + 2 + slot] = rs1; }
        __syncthreads();
        rs0 = red[r0 * 4 + 2] + red[r0 * 4 + 3];
        rs1 = red[r1 * 4 + 2] + red[r1 * 4 + 3];

        lrow[0] = lrow[0] * al0 + rs0; mrow[0] = mn0;
        lrow[1] = lrow[1] * al1 + rs1; mrow[1] = mn1;

        #pragma unroll
        for (int nt = 0; nt < 16; nt++) {
            o[nt][0] *= al0; o[nt][1] *= al0;
            o[nt][2] *= al1; o[nt][3] *= al1;
        }

        // ---- PV over this warp's t-half ----
        #pragma unroll
        for (int kc = 0; kc < 2; kc++) {
            uint32_t pa[4];
            pa[0] = pack_bf16x2(cs[2 * kc][0],     cs[2 * kc][1]);
            pa[1] = pack_bf16x2(cs[2 * kc][2],     cs[2 * kc][3]);
            pa[2] = pack_bf16x2(cs[2 * kc + 1][0], cs[2 * kc + 1][1]);
            pa[3] = pack_bf16x2(cs[2 * kc + 1][2], cs[2 * kc + 1][3]);
            #pragma unroll
            for (int ep = 0; ep < 8; ep++) {
                uint32_t vb4[4];
                uint32_t offV = (uint32_t)((wn + kc * 16 + vtrow) * 272 + (ep * 16 + vncol) * 2);
                LDSM_X4_T(vb4, vh_b + offV);
                MMA_BF16(o[2 * ep],     pa, &vb4[0]);
                MMA_BF16(o[2 * ep + 1], pa, &vb4[2]);
            }
        }
        buf ^= 1;
    }

    // ---- combine partner-warp partial o through (now dead) staging smem ----
    __syncthreads();
    float* red_o = (float*)Kh0;   // 8 pairs x 16 rows x 128 e = 64 KB
    const int pair = wid >> 1;
    if (slot == 0) {
        #pragma unroll
        for (int nt = 0; nt < 16; nt++) {
            int e = nt * 8 + 2 * tg;
            *(float2*)(red_o + pair * 2048 + gp * 128 + e)       = make_float2(o[nt][0], o[nt][1]);
            *(float2*)(red_o + pair * 2048 + (gp + 8) * 128 + e) = make_float2(o[nt][2], o[nt][3]);
        }
    }
    __syncthreads();
    if (slot == 1) {
        const int b_ = bh >> 3;
        float inv0 = 1.0f / lrow[0], inv1 = 1.0f / lrow[1];
        int sp0 = h * 128 + (sg0 >> 3), fp0 = (sg0 & 7) << 7;
        int sp1 = h * 128 + (sg1 >> 3), fp1 = (sg1 & 7) << 7;
        float* d0 = g_att + ((size_t)b_ * 1024 + sp0) * 1024 + fp0;
        float* d1 = g_att + ((size_t)b_ * 1024 + sp1) * 1024 + fp1;
        #pragma unroll
        for (int nt = 0; nt < 16; nt++) {
            int e = nt * 8 + 2 * tg;
            float2 p0 = *(float2*)(red_o + pair * 2048 + gp * 128 + e);
            float2 p1 = *(float2*)(red_o + pair * 2048 + (gp + 8) * 128 + e);
            *(float2*)(d0 + e) = make_float2((o[nt][0] + p0.x) * inv0, (o[nt][1] + p0.y) * inv0);
            *(float2*)(d1 + e) = make_float2((o[nt][2] + p1.x) * inv1, (o[nt][3] + p1.y) * inv1);
        }
    }
}

// ---------------- fused MLP + residual + LayerNorm (R13-proven) ----------------
__global__ __launch_bounds__(256) void mlp_ln_kernel(const float* __restrict__ X,
                                                     const float* __restrict__ Wm,
                                                     const float* __restrict__ gamma,
                                                     const float* __restrict__ beta,
                                                     float* __restrict__ out)
{
    __shared__ float At[32][32];
    __shared__ float Wt[32][128];
    const int m0 = blockIdx.x * 32;
    const int tid = threadIdx.x;
    const int tx = tid & 15, ty = tid >> 4;

    float acc[2][8] = {};

    for (int k0 = 0; k0 < 1024; k0 += 32) {
        __syncthreads();
        {
            int row = tid >> 3;
            int col = (tid & 7) << 2;
            *(float4*)(&At[row][col]) = *(const float4*)(g_att + (size_t)(m0 + row) * 1024 + k0 + col);
        }
        #pragma unroll
        for (int i = 0; i < 4; i++) {
            int f = tid + i * 256;
            int row = f >> 5;
            int col = (f & 31) << 2;
            *(float4*)(&Wt[row][col]) = *(const float4*)(Wm + (size_t)(k0 + row) * 128 + col);
        }
        __syncthreads();

        #pragma unroll
        for (int k4 = 0; k4 < 8; k4++) {
            float4 a[2];
            #pragma unroll
            for (int i = 0; i < 2; i++) a[i] = *(float4*)&At[ty * 2 + i][k4 * 4];
            float ws[4][8];
            #pragma unroll
            for (int kk = 0; kk < 4; kk++) {
                float4 u = *(float4*)&Wt[k4 * 4 + kk][tx * 8];
                float4 v = *(float4*)&Wt[k4 * 4 + kk][tx * 8 + 4];
                ws[kk][0] = u.x; ws[kk][1] = u.y; ws[kk][2] = u.z; ws[kk][3] = u.w;
                ws[kk][4] = v.x; ws[kk][5] = v.y; ws[kk][6] = v.z; ws[kk][7] = v.w;
            }
            #pragma unroll
            for (int i = 0; i < 2; i++)
                #pragma unroll
                for (int j = 0; j < 8; j++)
                    acc[i][j] += a[i].x * ws[0][j] + a[i].y * ws[1][j] + a[i].z * ws[2][j] + a[i].w * ws[3][j];
        }
    }

    float gj[8], bj[8];
    #pragma unroll
    for (int j = 0; j < 8; j++) { gj[j] = gamma[tx * 8 + j]; bj[j] = beta[tx * 8 + j]; }

    #pragma unroll
    for (int i = 0; i < 2; i++) {
        int r = m0 + ty * 2 + i;
        float y[8];
        float s = 0.f;
        #pragma unroll
        for (int j = 0; j < 8; j++) {
            y[j] = acc[i][j] + X[(size_t)r * 128 + tx * 8 + j];
            s += y[j];
        }
        #pragma unroll
        for (int off = 8; off; off >>= 1) s += __shfl_xor_sync(0xffffffffu, s, off);
        float mu = s * (1.0f / 128.0f);
        float vs = 0.f;
        #pragma unroll
        for (int j = 0; j < 8; j++) { float d = y[j] - mu; vs += d * d; }
        #pragma unroll
        for (int off = 8; off; off >>= 1) vs += __shfl_xor_sync(0xffffffffu, vs, off);
        float inv = rsqrtf(vs * (1.0f / 128.0f) + 1e-5f);
        #pragma unroll
        for (int j = 0; j < 8; j++)
            out[(size_t)r * 128 + tx * 8 + j] = (y[j] - mu) * inv * gj[j] + bj[j];
    }
}

// ---------------- launch ----------------
extern "C" void kernel_launch(void* const* d_in, const int* in_sizes, int n_in,
                              void* d_out, int out_size)
{
    const float* x     = (const float*)d_in[0];
    const float* memp  = (const float*)d_in[1];
    const float* u1    = (const float*)d_in[3];
    const float* u2    = (const float*)d_in[4];
    const float* w_q   = (const float*)d_in[5];
    const float* w_kv  = (const float*)d_in[6];
    const float* w_r   = (const float*)d_in[7];
    const float* w_mlp = (const float*)d_in[8];
    const float* ln_g  = (const float*)d_in[9];
    const float* ln_b  = (const float*)d_in[10];
    float* out = (float*)d_out;

    const int proj_smem  = (64 * 136 * 2 + 128 * 72 * 2) * 2;                      // 71,680 B
    const int ggemm_smem = (128 * 136 + 64 * 136 * 2) * 2;                         // 69,632 B
    const int attn_smem  = (128 * 136 * 2 + 2 * 64 * 136 * 3 + 2 * 128 * 80) * 2
                         + 2 * 128 * 4 + 128 * 4 * 4;                              // 218,112 B
    cudaFuncSetAttribute(proj_mma_kernel<0>, cudaFuncAttributeMaxDynamicSharedMemorySize, proj_smem);
    cudaFuncSetAttribute(proj_mma_kernel<1>, cudaFuncAttributeMaxDynamicSharedMemorySize, proj_smem);
    cudaFuncSetAttribute(proj_mma_kernel<2>, cudaFuncAttributeMaxDynamicSharedMemorySize, proj_smem);
    cudaFuncSetAttribute(ggemm_mma_kernel, cudaFuncAttributeMaxDynamicSharedMemorySize, ggemm_smem);
    cudaFuncSetAttribute(attn_kernel,      cudaFuncAttributeMaxDynamicSharedMemorySize, attn_smem);

    pos_kernel<<<1024, 256>>>();
    proj_mma_kernel<0><<<dim3(16, 64), 256, proj_smem>>>(x, nullptr, w_q, 1024);
    proj_mma_kernel<1><<<dim3(32, 128), 256, proj_smem>>>(x, memp, w_kv, 2048);
    proj_mma_kernel<2><<<dim3(16, 32), 256, proj_smem>>>(nullptr, nullptr, w_r, 1024);
    udot_kernel<<<8192, 256>>>(u1, 0, NB * NH * TOT);
    udot_kernel<<<2048, 256>>>(u2, 1, NH * TOT);
    ggemm_mma_kernel<<<dim3(32, 8, 32), 256, ggemm_smem>>>();
    attn_kernel<<<dim3(8, 32), 512, attn_smem>>>();
    mlp_ln_kernel<<<128, 256>>>(x, w_mlp, ln_g, ln_b, out);
}

// round 15
// speedup vs baseline: 1.0830x; 1.0830x over previous
#include <cuda_runtime.h>
#include <cuda_bf16.h>
#include <math.h>
#include <stdint.h>

#define NB 4
#define NH 8
#define SEGL 1024
#define TOT 2048
#define DD 128

// ---------------- scratch (device globals; no allocations) ----------------
__device__ float g_pos[TOT*DD];           // sinusoid table
__device__ __nv_bfloat16 g_qh[NB*NH*SEGL*DD];
__device__ __nv_bfloat16 g_ql[NB*NH*SEGL*DD];
__device__ __nv_bfloat16 g_kh[NB*NH*TOT*DD];
__device__ __nv_bfloat16 g_kl[NB*NH*TOT*DD];
__device__ __nv_bfloat16 g_vh[NB*NH*TOT*DD];   // V single bf16 plane
__device__ __nv_bfloat16 g_rh[NH*TOT*DD];
__device__ __nv_bfloat16 g_rl[NH*TOT*DD];
__device__ float g_u1k[NB*NH*TOT];
__device__ float g_u2r[NH*TOT];
__device__ float g_att[NB*SEGL*NH*DD];
__device__ __nv_bfloat16 g_G[(size_t)NB*NH*SEGL*TOT + 4096]; // +pad for aligned over-fetch

// ---------------- helpers ----------------
__device__ __forceinline__ uint32_t smem_u32(const void* p) {
    uint32_t a;
    asm("{ .reg .u64 t; cvta.to.shared.u64 t, %1; cvt.u32.u64 %0, t; }" : "=r"(a) : "l"(p));
    return a;
}
__device__ __forceinline__ uint32_t pack_bf16x2(float lo, float hi) {
    uint32_t d; asm("cvt.rn.bf16x2.f32 %0, %1, %2;" : "=r"(d) : "f"(hi), "f"(lo)); return d;
}
__device__ __forceinline__ void cp16(uint32_t dst, const void* src) {
    asm volatile("cp.async.cg.shared.global [%0], [%1], 16;" :: "r"(dst), "l"(src) : "memory");
}
#define CP_COMMIT() asm volatile("cp.async.commit_group;" ::: "memory")
#define CP_WAIT(n)  asm volatile("cp.async.wait_group %0;" :: "n"(n) : "memory")

#define LDSM_X4(r, addr) \
    asm volatile("ldmatrix.sync.aligned.m8n8.x4.shared.b16 {%0,%1,%2,%3}, [%4];" \
        : "=r"((r)[0]), "=r"((r)[1]), "=r"((r)[2]), "=r"((r)[3]) : "r"(addr))
#define LDSM_X4_T(r, addr) \
    asm volatile("ldmatrix.sync.aligned.m8n8.x4.trans.shared.b16 {%0,%1,%2,%3}, [%4];" \
        : "=r"((r)[0]), "=r"((r)[1]), "=r"((r)[2]), "=r"((r)[3]) : "r"(addr))
#define MMA_BF16(c, a, b) \
    asm volatile("mma.sync.aligned.m16n8k16.row.col.f32.bf16.bf16.f32 " \
        "{%0,%1,%2,%3}, {%4,%5,%6,%7}, {%8,%9}, {%0,%1,%2,%3};" \
        : "+f"((c)[0]), "+f"((c)[1]), "+f"((c)[2]), "+f"((c)[3]) \
        : "r"((a)[0]), "r"((a)[1]), "r"((a)[2]), "r"((a)[3]), "r"((b)[0]), "r"((b)[1]))

__device__ __forceinline__ void split4_bf16(float4 v, ushort4& hv, ushort4& lv) {
    __nv_bfloat16 b;
    b = __float2bfloat16(v.x); hv.x = __bfloat16_as_ushort(b);
    lv.x = __bfloat16_as_ushort(__float2bfloat16(v.x - __bfloat162float(b)));
    b = __float2bfloat16(v.y); hv.y = __bfloat16_as_ushort(b);
    lv.y = __bfloat16_as_ushort(__float2bfloat16(v.y - __bfloat162float(b)));
    b = __float2bfloat16(v.z); hv.z = __bfloat16_as_ushort(b);
    lv.z = __bfloat16_as_ushort(__float2bfloat16(v.z - __bfloat162float(b)));
    b = __float2bfloat16(v.w); hv.w = __bfloat16_as_ushort(b);
    lv.w = __bfloat16_as_ushort(__float2bfloat16(v.w - __bfloat162float(b)));
}
__device__ __forceinline__ void split2_bf16(float a, float b, ushort2& hv, ushort2& lv) {
    __nv_bfloat16 t;
    t = __float2bfloat16(a); hv.x = __bfloat16_as_ushort(t);
    lv.x = __bfloat16_as_ushort(__float2bfloat16(a - __bfloat162float(t)));
    t = __float2bfloat16(b); hv.y = __bfloat16_as_ushort(t);
    lv.y = __bfloat16_as_ushort(__float2bfloat16(b - __bfloat162float(t)));
}

// ---------------- sinusoid position table ----------------
__global__ __launch_bounds__(256) void pos_kernel()
{
    int idx = blockIdx.x * 256 + threadIdx.x;
    int m = idx >> 7, e = idx & 127;
    float pp = (float)(2047 - m);
    float ang = pp / powf(10000.0f, (float)(2 * e) * (1.0f / 128.0f));
    g_pos[idx] = ((e & 1) == 0) ? sinf(ang) : cosf(ang);
}

// ---------------- projection GEMMs: 64m x 64n tiles (R13-proven) ----------------
template<int MODE>
__global__ __launch_bounds__(256, 3) void proj_mma_kernel(const float* __restrict__ X,
                                                          const float* __restrict__ MEMI,
                                                          const float* __restrict__ W, int N)
{
    extern __shared__ __align__(16) unsigned short sm16[];
    unsigned short* Ah = sm16;              // 64*136
    unsigned short* Al = Ah + 64 * 136;
    unsigned short* Bh = Al + 64 * 136;     // 128*72 ([k][n])
    unsigned short* Bl = Bh + 128 * 72;

    const int m0 = blockIdx.y * 64;
    const int n0 = blockIdx.x * 64;
    const int tid = threadIdx.x, wid = tid >> 5, lane = tid & 31;

    #pragma unroll
    for (int i = 0; i < 8; i++) {
        int f = tid + i * 256;
        int row = f >> 5, col = (f & 31) << 2;
        int m = m0 + row;
        float4 a;
        if (MODE == 0) {
            a = *(const float4*)(X + (size_t)m * 128 + col);
        } else if (MODE == 1) {
            int bb = m >> 11, sp = m & 2047;
            const float* src = (sp < 1024) ? (MEMI + ((size_t)bb * 1024 + sp) * 128)
                                           : (X    + ((size_t)bb * 1024 + sp - 1024) * 128);
            a = *(const float4*)(src + col);
        } else {
            a = *(const float4*)(g_pos + (size_t)m * 128 + col);
        }
        ushort4 hv, lv;
        split4_bf16(a, hv, lv);
        *(ushort4*)(Ah + row * 136 + col) = hv;
        *(ushort4*)(Al + row * 136 + col) = lv;
    }
    #pragma unroll
    for (int i = 0; i < 8; i++) {
        int f = tid + i * 256;
        int row = f >> 4, col = (f & 15) << 2;
        float4 w = *(const float4*)(W + (size_t)row * N + n0 + col);
        ushort4 hv, lv;
        split4_bf16(w, hv, lv);
        *(ushort4*)(Bh + row * 72 + col) = hv;
        *(ushort4*)(Bl + row * 72 + col) = lv;
    }
    __syncthreads();

    const int wm = (wid >> 1) * 16;
    const int wn = (wid & 1) * 32;
    const int arow = (lane & 7) + ((lane >> 3) & 1) * 8;
    const int akoff = (lane >> 4) * 16;
    const int vtrow = ((lane >> 3) & 1) * 8 + (lane & 7);
    const int vncol = ((lane >> 4) & 1) * 8;

    const uint32_t ah_b = smem_u32(Ah), al_b = smem_u32(Al);
    const uint32_t bh_b = smem_u32(Bh), bl_b = smem_u32(Bl);

    float cs[4][4];
    #pragma unroll
    for (int nt = 0; nt < 4; nt++)
        #pragma unroll
        for (int e = 0; e < 4; e++) cs[nt][e] = 0.f;

    #pragma unroll
    for (int ks = 0; ks < 8; ks++) {
        uint32_t ah[4], al4[4];
        uint32_t offA = (uint32_t)((wm + arow) * 272 + ks * 32 + akoff);
        LDSM_X4(ah, ah_b + offA);
        LDSM_X4(al4, al_b + offA);
        #pragma unroll
        for (int np = 0; np < 2; np++) {
            uint32_t bh4[4], bl4[4];
            uint32_t offB = (uint32_t)((ks * 16 + vtrow) * 144 + (wn + np * 16 + vncol) * 2);
            LDSM_X4_T(bh4, bh_b + offB);
            LDSM_X4_T(bl4, bl_b + offB);
            MMA_BF16(cs[2 * np],     ah,  &bh4[0]);
            MMA_BF16(cs[2 * np],     ah,  &bl4[0]);
            MMA_BF16(cs[2 * np],     al4, &bh4[0]);
            MMA_BF16(cs[2 * np + 1], ah,  &bh4[2]);
            MMA_BF16(cs[2 * np + 1], ah,  &bl4[2]);
            MMA_BF16(cs[2 * np + 1], al4, &bh4[2]);
        }
    }

    const int gp = lane >> 2, tg = lane & 3;
    #pragma unroll
    for (int half = 0; half < 2; half++) {
        int m = m0 + wm + gp + 8 * half;
        #pragma unroll
        for (int nt = 0; nt < 4; nt++) {
            int col = wn + nt * 8 + 2 * tg;
            int fp = n0 + col;
            float v0 = cs[nt][2 * half], v1 = cs[nt][2 * half + 1];
            if (MODE == 0) {
                int b_ = m >> 10, sp = m & 1023;
                int h = sp >> 7;
                int s = ((sp & 127) << 3) + (fp >> 7);
                int e = fp & 127;
                size_t off = ((((size_t)b_ * 8 + h) * 1024 + s) << 7) + e;
                ushort2 hv, lv;
                split2_bf16(v0, v1, hv, lv);
                *(ushort2*)(g_qh + off) = hv;
                *(ushort2*)(g_ql + off) = lv;
            } else if (MODE == 1) {
                int bb = m >> 11, sp = m & 2047;
                int cc = bb * 2 + (sp >> 10);
                int h = (sp & 1023) >> 7;
                int t = ((sp & 127) << 4) + (fp >> 7);
                int e = fp & 127;
                if (cc < 4) {
                    size_t off = ((((size_t)cc * 8 + h) * 2048 + t) << 7) + e;
                    ushort2 hv, lv;
                    split2_bf16(v0, v1, hv, lv);
                    *(ushort2*)(g_kh + off) = hv;
                    *(ushort2*)(g_kl + off) = lv;
                } else {
                    size_t off = ((((size_t)(cc - 4) * 8 + h) * 2048 + t) << 7) + e;
                    ushort2 hv;
                    hv.x = __bfloat16_as_ushort(__float2bfloat16(v0));
                    hv.y = __bfloat16_as_ushort(__float2bfloat16(v1));
                    *(ushort2*)(g_vh + off) = hv;
                }
            } else {
                int h = m >> 8;
                int t = ((m & 255) << 3) + (fp >> 7);
                int e = fp & 127;
                size_t off = (((size_t)h * 2048 + t) << 7) + e;
                ushort2 hv, lv;
                split2_bf16(v0, v1, hv, lv);
                *(ushort2*)(g_rh + off) = hv;
                *(ushort2*)(g_rl + off) = lv;
            }
        }
    }
}

// ---------------- u1·k and u2·r from bf16 hi/lo planes ----------------
__global__ __launch_bounds__(256) void udot_kernel(const float* __restrict__ U, int which, int nrows)
{
    int row = blockIdx.x * 8 + (threadIdx.x >> 5);
    int lane = threadIdx.x & 31;
    if (row >= nrows) return;
    const __nv_bfloat16* Mh = which ? g_rh : g_kh;
    const __nv_bfloat16* Ml = which ? g_rl : g_kl;
    float* Out = which ? g_u2r : g_u1k;
    int h = (row >> 11) & 7;
    float4 u = *(const float4*)(U + h * 128 + lane * 4);
    ushort4 mh = *(const ushort4*)(Mh + (size_t)row * 128 + lane * 4);
    ushort4 ml = *(const ushort4*)(Ml + (size_t)row * 128 + lane * 4);
    float m0 = __bfloat162float(__ushort_as_bfloat16(mh.x)) + __bfloat162float(__ushort_as_bfloat16(ml.x));
    float m1 = __bfloat162float(__ushort_as_bfloat16(mh.y)) + __bfloat162float(__ushort_as_bfloat16(ml.y));
    float m2 = __bfloat162float(__ushort_as_bfloat16(mh.z)) + __bfloat162float(__ushort_as_bfloat16(ml.z));
    float m3 = __bfloat162float(__ushort_as_bfloat16(mh.w)) + __bfloat162float(__ushort_as_bfloat16(ml.w));
    float s = u.x * m0 + u.y * m1 + u.z * m2 + u.w * m3;
    #pragma unroll
    for (int o = 16; o; o >>= 1) s += __shfl_xor_sync(0xffffffffu, s, o);
    if (lane == 0) Out[row] = s;
}

// ---------------- banded G = qh.(rh+rl) via bf16 mma.sync (2-term, R14-proven) ----------------
__global__ __launch_bounds__(256, 2) void ggemm_mma_kernel()
{
    extern __shared__ __align__(16) unsigned short sm16[];
    unsigned short* Qh = sm16;              // 128*136
    unsigned short* Rh = Qh + 128 * 136;    // 64*136
    unsigned short* Rl = Rh + 64 * 136;

    const int rt = blockIdx.x, st = blockIdx.y, bh = blockIdx.z;
    if (rt < 14 - 2 * st) return;
    const int h = bh & 7;
    const int s0 = st * 128, r0 = rt * 64;
    const int tid = threadIdx.x, wid = tid >> 5, lane = tid & 31;

    const unsigned short* qh = (const unsigned short*)g_qh + ((size_t)bh * 1024 + s0) * 128;
    #pragma unroll
    for (int i = 0; i < 8; i++) {
        int f = tid + i * 256;
        int row = f >> 4, c8 = (f & 15) << 3;
        *(uint4*)(Qh + row * 136 + c8) = *(const uint4*)(qh + (size_t)row * 128 + c8);
    }
    const unsigned short* rh = (const unsigned short*)g_rh + ((size_t)h * 2048 + r0) * 128;
    const unsigned short* rl = (const unsigned short*)g_rl + ((size_t)h * 2048 + r0) * 128;
    #pragma unroll
    for (int i = 0; i < 4; i++) {
        int f = tid + i * 256;
        int row = f >> 4, c8 = (f & 15) << 3;
        *(uint4*)(Rh + row * 136 + c8) = *(const uint4*)(rh + (size_t)row * 128 + c8);
        *(uint4*)(Rl + row * 136 + c8) = *(const uint4*)(rl + (size_t)row * 128 + c8);
    }
    __syncthreads();

    const int wm = (wid >> 1) * 32;
    const int wn = (wid & 1) * 32;

    float c[2][4][4];
    #pragma unroll
    for (int mt = 0; mt < 2; mt++)
        #pragma unroll
        for (int nt = 0; nt < 4; nt++)
            #pragma unroll
            for (int e = 0; e < 4; e++) c[mt][nt][e] = 0.f;

    const int arow = (lane & 7) + ((lane >> 3) & 1) * 8;
    const int akoff = (lane >> 4) * 16;
    const int brow = lane & 7;
    const int bkoff = ((lane >> 3) & 1) * 16;

    const uint32_t qh_b = smem_u32(Qh);
    const uint32_t rh_b = smem_u32(Rh), rl_b = smem_u32(Rl);

    #pragma unroll
    for (int ks = 0; ks < 8; ks++) {
        uint32_t ah[2][4];
        #pragma unroll
        for (int mt = 0; mt < 2; mt++) {
            uint32_t off = (uint32_t)((wm + mt * 16 + arow) * 272 + ks * 32 + akoff);
            LDSM_X4(ah[mt], qh_b + off);
        }
        uint32_t bhf[4][2], blf[4][2];
        #pragma unroll
        for (int nt = 0; nt < 4; nt++) {
            uint32_t off = (uint32_t)((wn + nt * 8 + brow) * 272 + ks * 32 + bkoff);
            asm volatile("ldmatrix.sync.aligned.m8n8.x2.shared.b16 {%0,%1}, [%2];"
                : "=r"(bhf[nt][0]), "=r"(bhf[nt][1]) : "r"(rh_b + off));
            asm volatile("ldmatrix.sync.aligned.m8n8.x2.shared.b16 {%0,%1}, [%2];"
                : "=r"(blf[nt][0]), "=r"(blf[nt][1]) : "r"(rl_b + off));
        }
        #pragma unroll
        for (int mt = 0; mt < 2; mt++)
            #pragma unroll
            for (int nt = 0; nt < 4; nt++) {
                MMA_BF16(c[mt][nt], ah[mt], bhf[nt]);
                MMA_BF16(c[mt][nt], ah[mt], blf[nt]);
            }
    }

    const int gp = lane >> 2, tg = lane & 3;
    __nv_bfloat16* Gb = g_G + (size_t)bh * (1024 * 2048);
    #pragma unroll
    for (int mt = 0; mt < 2; mt++) {
        int mrow = s0 + wm + mt * 16 + gp;
        #pragma unroll
        for (int nt = 0; nt < 4; nt++) {
            int n = r0 + wn + nt * 8 + 2 * tg;
            *(uint32_t*)(Gb + (size_t)mrow * 2048 + n)       = pack_bf16x2(c[mt][nt][0], c[mt][nt][1]);
            *(uint32_t*)(Gb + (size_t)(mrow + 8) * 2048 + n) = pack_bf16x2(c[mt][nt][2], c[mt][nt][3]);
        }
    }
}

// ---------------- flash attention: 8 warps, cp.async double-buffered (R13-proven) ----------------
__global__ __launch_bounds__(256, 1) void attn_kernel()
{
    extern __shared__ __align__(16) char smraw[];
    unsigned short* Qh  = (unsigned short*)smraw;     // 128*136
    unsigned short* Ql  = Qh + 128 * 136;
    unsigned short* Kh0 = Ql + 128 * 136;             // 2 bufs x 64*136
    unsigned short* Kl0 = Kh0 + 2 * 64 * 136;
    unsigned short* Vh0 = Kl0 + 2 * 64 * 136;
    unsigned short* Gs0 = Vh0 + 2 * 64 * 136;         // 2 bufs x 128*80
    float* biasF = (float*)(Gs0 + 2 * 128 * 80);      // 2 bufs x 128 floats (u1k|u2r)

    const int st = 7 - blockIdx.x;                    // heavy-first
    const int bh = blockIdx.y, h = bh & 7;
    const int s0 = st * 128;
    const int tid = threadIdx.x;
    const int wid = tid >> 5, lane = tid & 31;
    const int wm = wid * 16;
    const int gp = lane >> 2, tg = lane & 3;
    const int arow = (lane & 7) + ((lane >> 3) & 1) * 8;
    const int akoff = (lane >> 4) * 16;
    const int b4row = ((lane >> 4) & 1) * 8 + (lane & 7);
    const int b4koff = ((lane >> 3) & 1) * 16;
    const int vtrow = ((lane >> 3) & 1) * 8 + (lane & 7);
    const int vncol = ((lane >> 4) & 1) * 8;

    const unsigned short* qhp = (const unsigned short*)g_qh + ((size_t)bh * 1024 + s0) * 128;
    const unsigned short* qlp = (const unsigned short*)g_ql + ((size_t)bh * 1024 + s0) * 128;
    const unsigned short* khp = (const unsigned short*)g_kh + (size_t)bh * (2048 * 128);
    const unsigned short* klp = (const unsigned short*)g_kl + (size_t)bh * (2048 * 128);
    const unsigned short* vhp = (const unsigned short*)g_vh + (size_t)bh * (2048 * 128);
    const unsigned short* Gbh = (const unsigned short*)g_G + (size_t)bh * (1024 * 2048);

    #pragma unroll
    for (int i = 0; i < 8; i++) {
        int f = tid + i * 256;
        int row = f >> 4, c8 = (f & 15) << 3;
        *(uint4*)(Qh + row * 136 + c8) = *(const uint4*)(qhp + (size_t)row * 128 + c8);
        *(uint4*)(Ql + row * 136 + c8) = *(const uint4*)(qlp + (size_t)row * 128 + c8);
    }

    const uint32_t qh_b = smem_u32(Qh), ql_b = smem_u32(Ql);
    const uint32_t khBase = smem_u32(Kh0), klBase = smem_u32(Kl0), vhBase = smem_u32(Vh0);
    const uint32_t gsBase = smem_u32(Gs0), biasBase = smem_u32(biasF);

    auto stage = [&](int b, int tt) {
        const int t0 = tt * 64;
        const uint32_t kh = khBase + b * 17408;
        const uint32_t kl = klBase + b * 17408;
        const uint32_t vh = vhBase + b * 17408;
        const uint32_t gs = gsBase + b * 20480;
        const uint32_t bb = biasBase + b * 512;
        #pragma unroll
        for (int i = 0; i < 12; i++) {
            int idx = tid + i * 256;
            int p = idx >> 10;
            int rc = idx & 1023;
            int row = rc >> 4, ch = rc & 15;
            uint32_t dst = (p == 0 ? kh : p == 1 ? kl : vh) + (uint32_t)(row * 272 + ch * 16);
            const unsigned short* src = (p == 0 ? khp : p == 1 ? klp : vhp)
                                      + (size_t)(t0 + row) * 128 + ch * 8;
            cp16(dst, src);
        }
        const int relbase = t0 - s0 + 1023;
        #pragma unroll
        for (int i = 0; i < 5; i++) {
            int idx = tid + i * 256;
            if (idx < 1152) {
                int row = idx / 9, ch = idx - row * 9;
                int start = (relbase - row) & ~7;
                cp16(gs + (uint32_t)(row * 160 + ch * 16),
                     Gbh + (size_t)(s0 + row) * 2048 + start + ch * 8);
            }
        }
        if (tid < 32) {
            int arr = tid >> 4, c = tid & 15;
            const float* src = arr ? (g_u2r + (size_t)h * 2048 + t0 + c * 4)
                                   : (g_u1k + (size_t)bh * 2048 + t0 + c * 4);
            cp16(bb + (uint32_t)(arr * 256 + c * 16), src);
        }
    };

    float o[16][4];
    #pragma unroll
    for (int nt = 0; nt < 16; nt++)
        #pragma unroll
        for (int e = 0; e < 4; e++) o[nt][e] = 0.f;

    float mrow[2], lrow[2];
    mrow[0] = mrow[1] = -1e30f;
    lrow[0] = lrow[1] = 0.f;

    const float scale = 0.08838834764831843f; // 1/sqrt(128)
    const int r0 = wm + gp, r1 = r0 + 8;
    const int sg0 = s0 + r0, sg1 = s0 + r1;

    const int ntiles = 2 * st + 18;
    stage(0, 0);
    CP_COMMIT();
    int buf = 0;

    for (int tt = 0; tt < ntiles; tt++) {
        __syncthreads();
        if (tt + 1 < ntiles) {
            stage(buf ^ 1, tt + 1);
            CP_COMMIT();
            CP_WAIT(1);
        } else {
            CP_WAIT(0);
        }
        __syncthreads();

        const int t0 = tt * 64;
        const int relbase = t0 - s0 + 1023;
        const uint32_t kh_b = khBase + buf * 17408;
        const uint32_t kl_b = klBase + buf * 17408;
        const uint32_t vh_b = vhBase + buf * 17408;
        const unsigned short* GsB = Gs0 + buf * 10240;
        const float* bA = biasF + buf * 128;
        const int off0 = (relbase - r0) & 7;
        const int off1 = (relbase - r1) & 7;

        float cs[8][4];
        #pragma unroll
        for (int nt = 0; nt < 8; nt++)
            #pragma unroll
            for (int e = 0; e < 4; e++) cs[nt][e] = 0.f;

        #pragma unroll
        for (int ks = 0; ks < 8; ks++) {
            uint32_t ah[4], al4[4];
            uint32_t offA = (uint32_t)((wm + arow) * 272 + ks * 32 + akoff);
            LDSM_X4(ah, qh_b + offA);
            LDSM_X4(al4, ql_b + offA);
            #pragma unroll
            for (int np = 0; np < 4; np++) {
                uint32_t bh4[4], bl4[4];
                uint32_t offB = (uint32_t)((np * 16 + b4row) * 272 + ks * 32 + b4koff);
                LDSM_X4(bh4, kh_b + offB);
                LDSM_X4(bl4, kl_b + offB);
                MMA_BF16(cs[2 * np],     ah,  &bh4[0]);
                MMA_BF16(cs[2 * np],     ah,  &bl4[0]);
                MMA_BF16(cs[2 * np],     al4, &bh4[0]);
                MMA_BF16(cs[2 * np + 1], ah,  &bh4[2]);
                MMA_BF16(cs[2 * np + 1], ah,  &bl4[2]);
                MMA_BF16(cs[2 * np + 1], al4, &bh4[2]);
            }
        }

        float mx0 = -1e30f, mx1 = -1e30f;
        #pragma unroll
        for (int nt = 0; nt < 8; nt++) {
            int col = nt * 8 + 2 * tg;
            int tgl = t0 + col;
            float b0 = bA[col] + bA[64 + col];
            float b1 = bA[col + 1] + bA[64 + col + 1];
            float g00 = __bfloat162float(*(const __nv_bfloat16*)(GsB + r0 * 80 + off0 + col));
            float g01 = __bfloat162float(*(const __nv_bfloat16*)(GsB + r0 * 80 + off0 + col + 1));
            float g10 = __bfloat162float(*(const __nv_bfloat16*)(GsB + r1 * 80 + off1 + col));
            float g11 = __bfloat162float(*(const __nv_bfloat16*)(GsB + r1 * 80 + off1 + col + 1));
            float v00 = (cs[nt][0] + g00 + b0) * scale;
            float v01 = (cs[nt][1] + g01 + b1) * scale;
            float v10 = (cs[nt][2] + g10 + b0) * scale;
            float v11 = (cs[nt][3] + g11 + b1) * scale;
            v00 = (tgl     - sg0 <= 1024) ? v00 : -1e30f;
            v01 = (tgl + 1 - sg0 <= 1024) ? v01 : -1e30f;
            v10 = (tgl     - sg1 <= 1024) ? v10 : -1e30f;
            v11 = (tgl + 1 - sg1 <= 1024) ? v11 : -1e30f;
            cs[nt][0] = v00; cs[nt][1] = v01; cs[nt][2] = v10; cs[nt][3] = v11;
            mx0 = fmaxf(mx0, fmaxf(v00, v01));
            mx1 = fmaxf(mx1, fmaxf(v10, v11));
        }
        mx0 = fmaxf(mx0, __shfl_xor_sync(0xffffffffu, mx0, 1));
        mx0 = fmaxf(mx0, __shfl_xor_sync(0xffffffffu, mx0, 2));
        mx1 = fmaxf(mx1, __shfl_xor_sync(0xffffffffu, mx1, 1));
        mx1 = fmaxf(mx1, __shfl_xor_sync(0xffffffffu, mx1, 2));

        float mn0 = fmaxf(mrow[0], mx0), mn1 = fmaxf(mrow[1], mx1);
        float al0 = __expf(mrow[0] - mn0), al1 = __expf(mrow[1] - mn1);
        float rs0 = 0.f, rs1 = 0.f;
        #pragma unroll
        for (int nt = 0; nt < 8; nt++) {
            float p00 = __expf(cs[nt][0] - mn0), p01 = __expf(cs[nt][1] - mn0);
            float p10 = __expf(cs[nt][2] - mn1), p11 = __expf(cs[nt][3] - mn1);
            rs0 += p00 + p01; rs1 += p10 + p11;
            cs[nt][0] = p00; cs[nt][1] = p01; cs[nt][2] = p10; cs[nt][3] = p11;
        }
        rs0 += __shfl_xor_sync(0xffffffffu, rs0, 1);
        rs0 += __shfl_xor_sync(0xffffffffu, rs0, 2);
        rs1 += __shfl_xor_sync(0xffffffffu, rs1, 1);
        rs1 += __shfl_xor_sync(0xffffffffu, rs1, 2);
        lrow[0] = lrow[0] * al0 + rs0; mrow[0] = mn0;
        lrow[1] = lrow[1] * al1 + rs1; mrow[1] = mn1;

        #pragma unroll
        for (int nt = 0; nt < 16; nt++) {
            o[nt][0] *= al0; o[nt][1] *= al0;
            o[nt][2] *= al1; o[nt][3] *= al1;
        }

        #pragma unroll
        for (int kc = 0; kc < 4; kc++) {
            uint32_t pa[4];
            pa[0] = pack_bf16x2(cs[2 * kc][0],     cs[2 * kc][1]);
            pa[1] = pack_bf16x2(cs[2 * kc][2],     cs[2 * kc][3]);
            pa[2] = pack_bf16x2(cs[2 * kc + 1][0], cs[2 * kc + 1][1]);
            pa[3] = pack_bf16x2(cs[2 * kc + 1][2], cs[2 * kc + 1][3]);
            #pragma unroll
            for (int ep = 0; ep < 8; ep++) {
                uint32_t vb4[4];
                uint32_t offV = (uint32_t)((kc * 16 + vtrow) * 272 + (ep * 16 + vncol) * 2);
                LDSM_X4_T(vb4, vh_b + offV);
                MMA_BF16(o[2 * ep],     pa, &vb4[0]);
                MMA_BF16(o[2 * ep + 1], pa, &vb4[2]);
            }
        }
        buf ^= 1;
    }

    const int b_ = bh >> 3;
    float inv0 = 1.0f / lrow[0], inv1 = 1.0f / lrow[1];
    {
        int sp0 = h * 128 + (sg0 >> 3), fp0 = (sg0 & 7) << 7;
        int sp1 = h * 128 + (sg1 >> 3), fp1 = (sg1 & 7) << 7;
        float* d0 = g_att + ((size_t)b_ * 1024 + sp0) * 1024 + fp0;
        float* d1 = g_att + ((size_t)b_ * 1024 + sp1) * 1024 + fp1;
        #pragma unroll
        for (int nt = 0; nt < 16; nt++) {
            int e = nt * 8 + 2 * tg;
            *(float2*)(d0 + e) = make_float2(o[nt][0] * inv0, o[nt][1] * inv0);
            *(float2*)(d1 + e) = make_float2(o[nt][2] * inv1, o[nt][3] * inv1);
        }
    }
}

// ---------------- fused MLP + residual + LayerNorm (R13-proven) ----------------
__global__ __launch_bounds__(256) void mlp_ln_kernel(const float* __restrict__ X,
                                                     const float* __restrict__ Wm,
                                                     const float* __restrict__ gamma,
                                                     const float* __restrict__ beta,
                                                     float* __restrict__ out)
{
    __shared__ float At[32][32];
    __shared__ float Wt[32][128];
    const int m0 = blockIdx.x * 32;
    const int tid = threadIdx.x;
    const int tx = tid & 15, ty = tid >> 4;

    float acc[2][8] = {};

    for (int k0 = 0; k0 < 1024; k0 += 32) {
        __syncthreads();
        {
            int row = tid >> 3;
            int col = (tid & 7) << 2;
            *(float4*)(&At[row][col]) = *(const float4*)(g_att + (size_t)(m0 + row) * 1024 + k0 + col);
        }
        #pragma unroll
        for (int i = 0; i < 4; i++) {
            int f = tid + i * 256;
            int row = f >> 5;
            int col = (f & 31) << 2;
            *(float4*)(&Wt[row][col]) = *(const float4*)(Wm + (size_t)(k0 + row) * 128 + col);
        }
        __syncthreads();

        #pragma unroll
        for (int k4 = 0; k4 < 8; k4++) {
            float4 a[2];
            #pragma unroll
            for (int i = 0; i < 2; i++) a[i] = *(float4*)&At[ty * 2 + i][k4 * 4];
            float ws[4][8];
            #pragma unroll
            for (int kk = 0; kk < 4; kk++) {
                float4 u = *(float4*)&Wt[k4 * 4 + kk][tx * 8];
                float4 v = *(float4*)&Wt[k4 * 4 + kk][tx * 8 + 4];
                ws[kk][0] = u.x; ws[kk][1] = u.y; ws[kk][2] = u.z; ws[kk][3] = u.w;
                ws[kk][4] = v.x; ws[kk][5] = v.y; ws[kk][6] = v.z; ws[kk][7] = v.w;
            }
            #pragma unroll
            for (int i = 0; i < 2; i++)
                #pragma unroll
                for (int j = 0; j < 8; j++)
                    acc[i][j] += a[i].x * ws[0][j] + a[i].y * ws[1][j] + a[i].z * ws[2][j] + a[i].w * ws[3][j];
        }
    }

    float gj[8], bj[8];
    #pragma unroll
    for (int j = 0; j < 8; j++) { gj[j] = gamma[tx * 8 + j]; bj[j] = beta[tx * 8 + j]; }

    #pragma unroll
    for (int i = 0; i < 2; i++) {
        int r = m0 + ty * 2 + i;
        float y[8];
        float s = 0.f;
        #pragma unroll
        for (int j = 0; j < 8; j++) {
            y[j] = acc[i][j] + X[(size_t)r * 128 + tx * 8 + j];
            s += y[j];
        }
        #pragma unroll
        for (int off = 8; off; off >>= 1) s += __shfl_xor_sync(0xffffffffu, s, off);
        float mu = s * (1.0f / 128.0f);
        float vs = 0.f;
        #pragma unroll
        for (int j = 0; j < 8; j++) { float d = y[j] - mu; vs += d * d; }
        #pragma unroll
        for (int off = 8; off; off >>= 1) vs += __shfl_xor_sync(0xffffffffu, vs, off);
        float inv = rsqrtf(vs * (1.0f / 128.0f) + 1e-5f);
        #pragma unroll
        for (int j = 0; j < 8; j++)
            out[(size_t)r * 128 + tx * 8 + j] = (y[j] - mu) * inv * gj[j] + bj[j];
    }
}

// ---------------- launch ----------------
extern "C" void kernel_launch(void* const* d_in, const int* in_sizes, int n_in,
                              void* d_out, int out_size)
{
    const float* x     = (const float*)d_in[0];
    const float* memp  = (const float*)d_in[1];
    const float* u1    = (const float*)d_in[3];
    const float* u2    = (const float*)d_in[4];
    const float* w_q   = (const float*)d_in[5];
    const float* w_kv  = (const float*)d_in[6];
    const float* w_r   = (const float*)d_in[7];
    const float* w_mlp = (const float*)d_in[8];
    const float* ln_g  = (const float*)d_in[9];
    const float* ln_b  = (const float*)d_in[10];
    float* out = (float*)d_out;

    const int proj_smem  = (64 * 136 * 2 + 128 * 72 * 2) * 2;                      // 71,680 B
    const int ggemm_smem = (128 * 136 + 64 * 136 * 2) * 2;                         // 69,632 B
    const int attn_smem  = (128 * 136 * 2 + 2 * 64 * 136 * 3 + 2 * 128 * 80) * 2
                         + 2 * 128 * 4;                                            // 216,064 B
    cudaFuncSetAttribute(proj_mma_kernel<0>, cudaFuncAttributeMaxDynamicSharedMemorySize, proj_smem);
    cudaFuncSetAttribute(proj_mma_kernel<1>, cudaFuncAttributeMaxDynamicSharedMemorySize, proj_smem);
    cudaFuncSetAttribute(proj_mma_kernel<2>, cudaFuncAttributeMaxDynamicSharedMemorySize, proj_smem);
    cudaFuncSetAttribute(ggemm_mma_kernel, cudaFuncAttributeMaxDynamicSharedMemorySize, ggemm_smem);
    cudaFuncSetAttribute(attn_kernel,      cudaFuncAttributeMaxDynamicSharedMemorySize, attn_smem);

    pos_kernel<<<1024, 256>>>();
    proj_mma_kernel<0><<<dim3(16, 64), 256, proj_smem>>>(x, nullptr, w_q, 1024);
    proj_mma_kernel<1><<<dim3(32, 128), 256, proj_smem>>>(x, memp, w_kv, 2048);
    proj_mma_kernel<2><<<dim3(16, 32), 256, proj_smem>>>(nullptr, nullptr, w_r, 1024);
    udot_kernel<<<8192, 256>>>(u1, 0, NB * NH * TOT);
    udot_kernel<<<2048, 256>>>(u2, 1, NH * TOT);
    ggemm_mma_kernel<<<dim3(32, 8, 32), 256, ggemm_smem>>>();
    attn_kernel<<<dim3(8, 32), 256, attn_smem>>>();
    mlp_ln_kernel<<<128, 256>>>(x, w_mlp, ln_g, ln_b, out);
}

// round 16
// speedup vs baseline: 1.1268x; 1.0404x over previous
#include <cuda_runtime.h>
#include <cuda_bf16.h>
#include <math.h>
#include <stdint.h>

#define NB 4
#define NH 8
#define SEGL 1024
#define TOT 2048
#define DD 128

// ---------------- scratch (device globals; no allocations) ----------------
__device__ float g_pos[TOT*DD];           // sinusoid table
__device__ __nv_bfloat16 g_qh[NB*NH*SEGL*DD];
__device__ __nv_bfloat16 g_kh[NB*NH*TOT*DD];
__device__ __nv_bfloat16 g_kl[NB*NH*TOT*DD];
__device__ __nv_bfloat16 g_vh[NB*NH*TOT*DD];   // V single bf16 plane
__device__ __nv_bfloat16 g_rh[NH*TOT*DD];
__device__ __nv_bfloat16 g_rl[NH*TOT*DD];
__device__ float g_u1k[NB*NH*TOT];
__device__ float g_u2r[NH*TOT];
__device__ float g_att[NB*SEGL*NH*DD];
__device__ __nv_bfloat16 g_G[(size_t)NB*NH*SEGL*TOT + 4096]; // +pad for aligned over-fetch

// ---------------- helpers ----------------
__device__ __forceinline__ uint32_t smem_u32(const void* p) {
    uint32_t a;
    asm("{ .reg .u64 t; cvta.to.shared.u64 t, %1; cvt.u32.u64 %0, t; }" : "=r"(a) : "l"(p));
    return a;
}
__device__ __forceinline__ uint32_t pack_bf16x2(float lo, float hi) {
    uint32_t d; asm("cvt.rn.bf16x2.f32 %0, %1, %2;" : "=r"(d) : "f"(hi), "f"(lo)); return d;
}
__device__ __forceinline__ void cp16(uint32_t dst, const void* src) {
    asm volatile("cp.async.cg.shared.global [%0], [%1], 16;" :: "r"(dst), "l"(src) : "memory");
}
#define CP_COMMIT() asm volatile("cp.async.commit_group;" ::: "memory")
#define CP_WAIT(n)  asm volatile("cp.async.wait_group %0;" :: "n"(n) : "memory")

#define LDSM_X4(r, addr) \
    asm volatile("ldmatrix.sync.aligned.m8n8.x4.shared.b16 {%0,%1,%2,%3}, [%4];" \
        : "=r"((r)[0]), "=r"((r)[1]), "=r"((r)[2]), "=r"((r)[3]) : "r"(addr))
#define LDSM_X4_T(r, addr) \
    asm volatile("ldmatrix.sync.aligned.m8n8.x4.trans.shared.b16 {%0,%1,%2,%3}, [%4];" \
        : "=r"((r)[0]), "=r"((r)[1]), "=r"((r)[2]), "=r"((r)[3]) : "r"(addr))
#define MMA_BF16(c, a, b) \
    asm volatile("mma.sync.aligned.m16n8k16.row.col.f32.bf16.bf16.f32 " \
        "{%0,%1,%2,%3}, {%4,%5,%6,%7}, {%8,%9}, {%0,%1,%2,%3};" \
        : "+f"((c)[0]), "+f"((c)[1]), "+f"((c)[2]), "+f"((c)[3]) \
        : "r"((a)[0]), "r"((a)[1]), "r"((a)[2]), "r"((a)[3]), "r"((b)[0]), "r"((b)[1]))

__device__ __forceinline__ void split4_bf16(float4 v, ushort4& hv, ushort4& lv) {
    __nv_bfloat16 b;
    b = __float2bfloat16(v.x); hv.x = __bfloat16_as_ushort(b);
    lv.x = __bfloat16_as_ushort(__float2bfloat16(v.x - __bfloat162float(b)));
    b = __float2bfloat16(v.y); hv.y = __bfloat16_as_ushort(b);
    lv.y = __bfloat16_as_ushort(__float2bfloat16(v.y - __bfloat162float(b)));
    b = __float2bfloat16(v.z); hv.z = __bfloat16_as_ushort(b);
    lv.z = __bfloat16_as_ushort(__float2bfloat16(v.z - __bfloat162float(b)));
    b = __float2bfloat16(v.w); hv.w = __bfloat16_as_ushort(b);
    lv.w = __bfloat16_as_ushort(__float2bfloat16(v.w - __bfloat162float(b)));
}
__device__ __forceinline__ void split2_bf16(float a, float b, ushort2& hv, ushort2& lv) {
    __nv_bfloat16 t;
    t = __float2bfloat16(a); hv.x = __bfloat16_as_ushort(t);
    lv.x = __bfloat16_as_ushort(__float2bfloat16(a - __bfloat162float(t)));
    t = __float2bfloat16(b); hv.y = __bfloat16_as_ushort(t);
    lv.y = __bfloat16_as_ushort(__float2bfloat16(b - __bfloat162float(t)));
}

// ---------------- sinusoid position table ----------------
__global__ __launch_bounds__(256) void pos_kernel()
{
    int idx = blockIdx.x * 256 + threadIdx.x;
    int m = idx >> 7, e = idx & 127;
    float pp = (float)(2047 - m);
    float ang = pp / powf(10000.0f, (float)(2 * e) * (1.0f / 128.0f));
    g_pos[idx] = ((e & 1) == 0) ? sinf(ang) : cosf(ang);
}

// ---------------- projection GEMMs: 64m x 64n tiles (R13-proven) ----------------
template<int MODE>
__global__ __launch_bounds__(256, 3) void proj_mma_kernel(const float* __restrict__ X,
                                                          const float* __restrict__ MEMI,
                                                          const float* __restrict__ W, int N)
{
    extern __shared__ __align__(16) unsigned short sm16[];
    unsigned short* Ah = sm16;              // 64*136
    unsigned short* Al = Ah + 64 * 136;
    unsigned short* Bh = Al + 64 * 136;     // 128*72 ([k][n])
    unsigned short* Bl = Bh + 128 * 72;

    const int m0 = blockIdx.y * 64;
    const int n0 = blockIdx.x * 64;
    const int tid = threadIdx.x, wid = tid >> 5, lane = tid & 31;

    #pragma unroll
    for (int i = 0; i < 8; i++) {
        int f = tid + i * 256;
        int row = f >> 5, col = (f & 31) << 2;
        int m = m0 + row;
        float4 a;
        if (MODE == 0) {
            a = *(const float4*)(X + (size_t)m * 128 + col);
        } else if (MODE == 1) {
            int bb = m >> 11, sp = m & 2047;
            const float* src = (sp < 1024) ? (MEMI + ((size_t)bb * 1024 + sp) * 128)
                                           : (X    + ((size_t)bb * 1024 + sp - 1024) * 128);
            a = *(const float4*)(src + col);
        } else {
            a = *(const float4*)(g_pos + (size_t)m * 128 + col);
        }
        ushort4 hv, lv;
        split4_bf16(a, hv, lv);
        *(ushort4*)(Ah + row * 136 + col) = hv;
        *(ushort4*)(Al + row * 136 + col) = lv;
    }
    #pragma unroll
    for (int i = 0; i < 8; i++) {
        int f = tid + i * 256;
        int row = f >> 4, col = (f & 15) << 2;
        float4 w = *(const float4*)(W + (size_t)row * N + n0 + col);
        ushort4 hv, lv;
        split4_bf16(w, hv, lv);
        *(ushort4*)(Bh + row * 72 + col) = hv;
        *(ushort4*)(Bl + row * 72 + col) = lv;
    }
    __syncthreads();

    const int wm = (wid >> 1) * 16;
    const int wn = (wid & 1) * 32;
    const int arow = (lane & 7) + ((lane >> 3) & 1) * 8;
    const int akoff = (lane >> 4) * 16;
    const int vtrow = ((lane >> 3) & 1) * 8 + (lane & 7);
    const int vncol = ((lane >> 4) & 1) * 8;

    const uint32_t ah_b = smem_u32(Ah), al_b = smem_u32(Al);
    const uint32_t bh_b = smem_u32(Bh), bl_b = smem_u32(Bl);

    float cs[4][4];
    #pragma unroll
    for (int nt = 0; nt < 4; nt++)
        #pragma unroll
        for (int e = 0; e < 4; e++) cs[nt][e] = 0.f;

    #pragma unroll
    for (int ks = 0; ks < 8; ks++) {
        uint32_t ah[4], al4[4];
        uint32_t offA = (uint32_t)((wm + arow) * 272 + ks * 32 + akoff);
        LDSM_X4(ah, ah_b + offA);
        LDSM_X4(al4, al_b + offA);
        #pragma unroll
        for (int np = 0; np < 2; np++) {
            uint32_t bh4[4], bl4[4];
            uint32_t offB = (uint32_t)((ks * 16 + vtrow) * 144 + (wn + np * 16 + vncol) * 2);
            LDSM_X4_T(bh4, bh_b + offB);
            LDSM_X4_T(bl4, bl_b + offB);
            MMA_BF16(cs[2 * np],     ah,  &bh4[0]);
            MMA_BF16(cs[2 * np],     ah,  &bl4[0]);
            MMA_BF16(cs[2 * np],     al4, &bh4[0]);
            MMA_BF16(cs[2 * np + 1], ah,  &bh4[2]);
            MMA_BF16(cs[2 * np + 1], ah,  &bl4[2]);
            MMA_BF16(cs[2 * np + 1], al4, &bh4[2]);
        }
    }

    const int gp = lane >> 2, tg = lane & 3;
    #pragma unroll
    for (int half = 0; half < 2; half++) {
        int m = m0 + wm + gp + 8 * half;
        #pragma unroll
        for (int nt = 0; nt < 4; nt++) {
            int col = wn + nt * 8 + 2 * tg;
            int fp = n0 + col;
            float v0 = cs[nt][2 * half], v1 = cs[nt][2 * half + 1];
            if (MODE == 0) {
                int b_ = m >> 10, sp = m & 1023;
                int h = sp >> 7;
                int s = ((sp & 127) << 3) + (fp >> 7);
                int e = fp & 127;
                size_t off = ((((size_t)b_ * 8 + h) * 1024 + s) << 7) + e;
                ushort2 hv;
                hv.x = __bfloat16_as_ushort(__float2bfloat16(v0));
                hv.y = __bfloat16_as_ushort(__float2bfloat16(v1));
                *(ushort2*)(g_qh + off) = hv;
            } else if (MODE == 1) {
                int bb = m >> 11, sp = m & 2047;
                int cc = bb * 2 + (sp >> 10);
                int h = (sp & 1023) >> 7;
                int t = ((sp & 127) << 4) + (fp >> 7);
                int e = fp & 127;
                if (cc < 4) {
                    size_t off = ((((size_t)cc * 8 + h) * 2048 + t) << 7) + e;
                    ushort2 hv, lv;
                    split2_bf16(v0, v1, hv, lv);
                    *(ushort2*)(g_kh + off) = hv;
                    *(ushort2*)(g_kl + off) = lv;
                } else {
                    size_t off = ((((size_t)(cc - 4) * 8 + h) * 2048 + t) << 7) + e;
                    ushort2 hv;
                    hv.x = __bfloat16_as_ushort(__float2bfloat16(v0));
                    hv.y = __bfloat16_as_ushort(__float2bfloat16(v1));
                    *(ushort2*)(g_vh + off) = hv;
                }
            } else {
                int h = m >> 8;
                int t = ((m & 255) << 3) + (fp >> 7);
                int e = fp & 127;
                size_t off = (((size_t)h * 2048 + t) << 7) + e;
                ushort2 hv, lv;
                split2_bf16(v0, v1, hv, lv);
                *(ushort2*)(g_rh + off) = hv;
                *(ushort2*)(g_rl + off) = lv;
            }
        }
    }
}

// ---------------- u1·k and u2·r from bf16 hi/lo planes ----------------
__global__ __launch_bounds__(256) void udot_kernel(const float* __restrict__ U, int which, int nrows)
{
    int row = blockIdx.x * 8 + (threadIdx.x >> 5);
    int lane = threadIdx.x & 31;
    if (row >= nrows) return;
    const __nv_bfloat16* Mh = which ? g_rh : g_kh;
    const __nv_bfloat16* Ml = which ? g_rl : g_kl;
    float* Out = which ? g_u2r : g_u1k;
    int h = (row >> 11) & 7;
    float4 u = *(const float4*)(U + h * 128 + lane * 4);
    ushort4 mh = *(const ushort4*)(Mh + (size_t)row * 128 + lane * 4);
    ushort4 ml = *(const ushort4*)(Ml + (size_t)row * 128 + lane * 4);
    float m0 = __bfloat162float(__ushort_as_bfloat16(mh.x)) + __bfloat162float(__ushort_as_bfloat16(ml.x));
    float m1 = __bfloat162float(__ushort_as_bfloat16(mh.y)) + __bfloat162float(__ushort_as_bfloat16(ml.y));
    float m2 = __bfloat162float(__ushort_as_bfloat16(mh.z)) + __bfloat162float(__ushort_as_bfloat16(ml.z));
    float m3 = __bfloat162float(__ushort_as_bfloat16(mh.w)) + __bfloat162float(__ushort_as_bfloat16(ml.w));
    float s = u.x * m0 + u.y * m1 + u.z * m2 + u.w * m3;
    #pragma unroll
    for (int o = 16; o; o >>= 1) s += __shfl_xor_sync(0xffffffffu, s, o);
    if (lane == 0) Out[row] = s;
}

// ---------------- banded G = qh.(rh+rl) via bf16 mma.sync (2-term, R15-proven) ----------------
__global__ __launch_bounds__(256, 2) void ggemm_mma_kernel()
{
    extern __shared__ __align__(16) unsigned short sm16[];
    unsigned short* Qh = sm16;              // 128*136
    unsigned short* Rh = Qh + 128 * 136;    // 64*136
    unsigned short* Rl = Rh + 64 * 136;

    const int rt = blockIdx.x, st = blockIdx.y, bh = blockIdx.z;
    if (rt < 14 - 2 * st) return;
    const int h = bh & 7;
    const int s0 = st * 128, r0 = rt * 64;
    const int tid = threadIdx.x, wid = tid >> 5, lane = tid & 31;

    const unsigned short* qh = (const unsigned short*)g_qh + ((size_t)bh * 1024 + s0) * 128;
    #pragma unroll
    for (int i = 0; i < 8; i++) {
        int f = tid + i * 256;
        int row = f >> 4, c8 = (f & 15) << 3;
        *(uint4*)(Qh + row * 136 + c8) = *(const uint4*)(qh + (size_t)row * 128 + c8);
    }
    const unsigned short* rh = (const unsigned short*)g_rh + ((size_t)h * 2048 + r0) * 128;
    const unsigned short* rl = (const unsigned short*)g_rl + ((size_t)h * 2048 + r0) * 128;
    #pragma unroll
    for (int i = 0; i < 4; i++) {
        int f = tid + i * 256;
        int row = f >> 4, c8 = (f & 15) << 3;
        *(uint4*)(Rh + row * 136 + c8) = *(const uint4*)(rh + (size_t)row * 128 + c8);
        *(uint4*)(Rl + row * 136 + c8) = *(const uint4*)(rl + (size_t)row * 128 + c8);
    }
    __syncthreads();

    const int wm = (wid >> 1) * 32;
    const int wn = (wid & 1) * 32;

    float c[2][4][4];
    #pragma unroll
    for (int mt = 0; mt < 2; mt++)
        #pragma unroll
        for (int nt = 0; nt < 4; nt++)
            #pragma unroll
            for (int e = 0; e < 4; e++) c[mt][nt][e] = 0.f;

    const int arow = (lane & 7) + ((lane >> 3) & 1) * 8;
    const int akoff = (lane >> 4) * 16;
    const int brow = lane & 7;
    const int bkoff = ((lane >> 3) & 1) * 16;

    const uint32_t qh_b = smem_u32(Qh);
    const uint32_t rh_b = smem_u32(Rh), rl_b = smem_u32(Rl);

    #pragma unroll
    for (int ks = 0; ks < 8; ks++) {
        uint32_t ah[2][4];
        #pragma unroll
        for (int mt = 0; mt < 2; mt++) {
            uint32_t off = (uint32_t)((wm + mt * 16 + arow) * 272 + ks * 32 + akoff);
            LDSM_X4(ah[mt], qh_b + off);
        }
        uint32_t bhf[4][2], blf[4][2];
        #pragma unroll
        for (int nt = 0; nt < 4; nt++) {
            uint32_t off = (uint32_t)((wn + nt * 8 + brow) * 272 + ks * 32 + bkoff);
            asm volatile("ldmatrix.sync.aligned.m8n8.x2.shared.b16 {%0,%1}, [%2];"
                : "=r"(bhf[nt][0]), "=r"(bhf[nt][1]) : "r"(rh_b + off));
            asm volatile("ldmatrix.sync.aligned.m8n8.x2.shared.b16 {%0,%1}, [%2];"
                : "=r"(blf[nt][0]), "=r"(blf[nt][1]) : "r"(rl_b + off));
        }
        #pragma unroll
        for (int mt = 0; mt < 2; mt++)
            #pragma unroll
            for (int nt = 0; nt < 4; nt++) {
                MMA_BF16(c[mt][nt], ah[mt], bhf[nt]);
                MMA_BF16(c[mt][nt], ah[mt], blf[nt]);
            }
    }

    const int gp = lane >> 2, tg = lane & 3;
    __nv_bfloat16* Gb = g_G + (size_t)bh * (1024 * 2048);
    #pragma unroll
    for (int mt = 0; mt < 2; mt++) {
        int mrow = s0 + wm + mt * 16 + gp;
        #pragma unroll
        for (int nt = 0; nt < 4; nt++) {
            int n = r0 + wn + nt * 8 + 2 * tg;
            *(uint32_t*)(Gb + (size_t)mrow * 2048 + n)       = pack_bf16x2(c[mt][nt][0], c[mt][nt][1]);
            *(uint32_t*)(Gb + (size_t)(mrow + 8) * 2048 + n) = pack_bf16x2(c[mt][nt][2], c[mt][nt][3]);
        }
    }
}

// ---------------- flash attention: 8 warps, 2-term QK (qh only), cp.async pipeline ----------------
__global__ __launch_bounds__(256, 1) void attn_kernel()
{
    extern __shared__ __align__(16) char smraw[];
    unsigned short* Qh  = (unsigned short*)smraw;     // 128*136
    unsigned short* Kh0 = Qh + 128 * 136;             // 2 bufs x 64*136
    unsigned short* Kl0 = Kh0 + 2 * 64 * 136;
    unsigned short* Vh0 = Kl0 + 2 * 64 * 136;
    unsigned short* Gs0 = Vh0 + 2 * 64 * 136;         // 2 bufs x 128*80
    float* biasF = (float*)(Gs0 + 2 * 128 * 80);      // 2 bufs x 128 floats (u1k|u2r)

    const int st = 7 - blockIdx.x;                    // heavy-first
    const int bh = blockIdx.y, h = bh & 7;
    const int s0 = st * 128;
    const int tid = threadIdx.x;
    const int wid = tid >> 5, lane = tid & 31;
    const int wm = wid * 16;
    const int gp = lane >> 2, tg = lane & 3;
    const int arow = (lane & 7) + ((lane >> 3) & 1) * 8;
    const int akoff = (lane >> 4) * 16;
    const int b4row = ((lane >> 4) & 1) * 8 + (lane & 7);
    const int b4koff = ((lane >> 3) & 1) * 16;
    const int vtrow = ((lane >> 3) & 1) * 8 + (lane & 7);
    const int vncol = ((lane >> 4) & 1) * 8;

    const unsigned short* qhp = (const unsigned short*)g_qh + ((size_t)bh * 1024 + s0) * 128;
    const unsigned short* khp = (const unsigned short*)g_kh + (size_t)bh * (2048 * 128);
    const unsigned short* klp = (const unsigned short*)g_kl + (size_t)bh * (2048 * 128);
    const unsigned short* vhp = (const unsigned short*)g_vh + (size_t)bh * (2048 * 128);
    const unsigned short* Gbh = (const unsigned short*)g_G + (size_t)bh * (1024 * 2048);

    #pragma unroll
    for (int i = 0; i < 8; i++) {
        int f = tid + i * 256;
        int row = f >> 4, c8 = (f & 15) << 3;
        *(uint4*)(Qh + row * 136 + c8) = *(const uint4*)(qhp + (size_t)row * 128 + c8);
    }

    const uint32_t qh_b = smem_u32(Qh);
    const uint32_t khBase = smem_u32(Kh0), klBase = smem_u32(Kl0), vhBase = smem_u32(Vh0);
    const uint32_t gsBase = smem_u32(Gs0), biasBase = smem_u32(biasF);

    auto stage = [&](int b, int tt) {
        const int t0 = tt * 64;
        const uint32_t kh = khBase + b * 17408;
        const uint32_t kl = klBase + b * 17408;
        const uint32_t vh = vhBase + b * 17408;
        const uint32_t gs = gsBase + b * 20480;
        const uint32_t bb = biasBase + b * 512;
        #pragma unroll
        for (int i = 0; i < 12; i++) {
            int idx = tid + i * 256;
            int p = idx >> 10;
            int rc = idx & 1023;
            int row = rc >> 4, ch = rc & 15;
            uint32_t dst = (p == 0 ? kh : p == 1 ? kl : vh) + (uint32_t)(row * 272 + ch * 16);
            const unsigned short* src = (p == 0 ? khp : p == 1 ? klp : vhp)
                                      + (size_t)(t0 + row) * 128 + ch * 8;
            cp16(dst, src);
        }
        const int relbase = t0 - s0 + 1023;
        #pragma unroll
        for (int i = 0; i < 5; i++) {
            int idx = tid + i * 256;
            if (idx < 1152) {
                int row = idx / 9, ch = idx - row * 9;
                int start = (relbase - row) & ~7;
                cp16(gs + (uint32_t)(row * 160 + ch * 16),
                     Gbh + (size_t)(s0 + row) * 2048 + start + ch * 8);
            }
        }
        if (tid < 32) {
            int arr = tid >> 4, c = tid & 15;
            const float* src = arr ? (g_u2r + (size_t)h * 2048 + t0 + c * 4)
                                   : (g_u1k + (size_t)bh * 2048 + t0 + c * 4);
            cp16(bb + (uint32_t)(arr * 256 + c * 16), src);
        }
    };

    float o[16][4];
    #pragma unroll
    for (int nt = 0; nt < 16; nt++)
        #pragma unroll
        for (int e = 0; e < 4; e++) o[nt][e] = 0.f;

    float mrow[2], lrow[2];
    mrow[0] = mrow[1] = -1e30f;
    lrow[0] = lrow[1] = 0.f;

    const float scale = 0.08838834764831843f; // 1/sqrt(128)
    const int r0 = wm + gp, r1 = r0 + 8;
    const int sg0 = s0 + r0, sg1 = s0 + r1;

    const int ntiles = 2 * st + 18;
    stage(0, 0);
    CP_COMMIT();
    int buf = 0;

    for (int tt = 0; tt < ntiles; tt++) {
        __syncthreads();
        if (tt + 1 < ntiles) {
            stage(buf ^ 1, tt + 1);
            CP_COMMIT();
            CP_WAIT(1);
        } else {
            CP_WAIT(0);
        }
        __syncthreads();

        const int t0 = tt * 64;
        const int relbase = t0 - s0 + 1023;
        const uint32_t kh_b = khBase + buf * 17408;
        const uint32_t kl_b = klBase + buf * 17408;
        const uint32_t vh_b = vhBase + buf * 17408;
        const unsigned short* GsB = Gs0 + buf * 10240;
        const float* bA = biasF + buf * 128;
        const int off0 = (relbase - r0) & 7;
        const int off1 = (relbase - r1) & 7;

        // ---- QK (2-term: qh.kh + qh.kl = qh.k) ----
        float cs[8][4];
        #pragma unroll
        for (int nt = 0; nt < 8; nt++)
            #pragma unroll
            for (int e = 0; e < 4; e++) cs[nt][e] = 0.f;

        #pragma unroll
        for (int ks = 0; ks < 8; ks++) {
            uint32_t ah[4];
            uint32_t offA = (uint32_t)((wm + arow) * 272 + ks * 32 + akoff);
            LDSM_X4(ah, qh_b + offA);
            #pragma unroll
            for (int np = 0; np < 4; np++) {
                uint32_t bh4[4], bl4[4];
                uint32_t offB = (uint32_t)((np * 16 + b4row) * 272 + ks * 32 + b4koff);
                LDSM_X4(bh4, kh_b + offB);
                LDSM_X4(bl4, kl_b + offB);
                MMA_BF16(cs[2 * np],     ah, &bh4[0]);
                MMA_BF16(cs[2 * np],     ah, &bl4[0]);
                MMA_BF16(cs[2 * np + 1], ah, &bh4[2]);
                MMA_BF16(cs[2 * np + 1], ah, &bl4[2]);
            }
        }

        float mx0 = -1e30f, mx1 = -1e30f;
        #pragma unroll
        for (int nt = 0; nt < 8; nt++) {
            int col = nt * 8 + 2 * tg;
            int tgl = t0 + col;
            float b0 = bA[col] + bA[64 + col];
            float b1 = bA[col + 1] + bA[64 + col + 1];
            float g00 = __bfloat162float(*(const __nv_bfloat16*)(GsB + r0 * 80 + off0 + col));
            float g01 = __bfloat162float(*(const __nv_bfloat16*)(GsB + r0 * 80 + off0 + col + 1));
            float g10 = __bfloat162float(*(const __nv_bfloat16*)(GsB + r1 * 80 + off1 + col));
            float g11 = __bfloat162float(*(const __nv_bfloat16*)(GsB + r1 * 80 + off1 + col + 1));
            float v00 = (cs[nt][0] + g00 + b0) * scale;
            float v01 = (cs[nt][1] + g01 + b1) * scale;
            float v10 = (cs[nt][2] + g10 + b0) * scale;
            float v11 = (cs[nt][3] + g11 + b1) * scale;
            v00 = (tgl     - sg0 <= 1024) ? v00 : -1e30f;
            v01 = (tgl + 1 - sg0 <= 1024) ? v01 : -1e30f;
            v10 = (tgl     - sg1 <= 1024) ? v10 : -1e30f;
            v11 = (tgl + 1 - sg1 <= 1024) ? v11 : -1e30f;
            cs[nt][0] = v00; cs[nt][1] = v01; cs[nt][2] = v10; cs[nt][3] = v11;
            mx0 = fmaxf(mx0, fmaxf(v00, v01));
            mx1 = fmaxf(mx1, fmaxf(v10, v11));
        }
        mx0 = fmaxf(mx0, __shfl_xor_sync(0xffffffffu, mx0, 1));
        mx0 = fmaxf(mx0, __shfl_xor_sync(0xffffffffu, mx0, 2));
        mx1 = fmaxf(mx1, __shfl_xor_sync(0xffffffffu, mx1, 1));
        mx1 = fmaxf(mx1, __shfl_xor_sync(0xffffffffu, mx1, 2));

        float mn0 = fmaxf(mrow[0], mx0), mn1 = fmaxf(mrow[1], mx1);
        float al0 = __expf(mrow[0] - mn0), al1 = __expf(mrow[1] - mn1);
        float rs0 = 0.f, rs1 = 0.f;
        #pragma unroll
        for (int nt = 0; nt < 8; nt++) {
            float p00 = __expf(cs[nt][0] - mn0), p01 = __expf(cs[nt][1] - mn0);
            float p10 = __expf(cs[nt][2] - mn1), p11 = __expf(cs[nt][3] - mn1);
            rs0 += p00 + p01; rs1 += p10 + p11;
            cs[nt][0] = p00; cs[nt][1] = p01; cs[nt][2] = p10; cs[nt][3] = p11;
        }
        rs0 += __shfl_xor_sync(0xffffffffu, rs0, 1);
        rs0 += __shfl_xor_sync(0xffffffffu, rs0, 2);
        rs1 += __shfl_xor_sync(0xffffffffu, rs1, 1);
        rs1 += __shfl_xor_sync(0xffffffffu, rs1, 2);
        lrow[0] = lrow[0] * al0 + rs0; mrow[0] = mn0;
        lrow[1] = lrow[1] * al1 + rs1; mrow[1] = mn1;

        #pragma unroll
        for (int nt = 0; nt < 16; nt++) {
            o[nt][0] *= al0; o[nt][1] *= al0;
            o[nt][2] *= al1; o[nt][3] *= al1;
        }

        #pragma unroll
        for (int kc = 0; kc < 4; kc++) {
            uint32_t pa[4];
            pa[0] = pack_bf16x2(cs[2 * kc][0],     cs[2 * kc][1]);
            pa[1] = pack_bf16x2(cs[2 * kc][2],     cs[2 * kc][3]);
            pa[2] = pack_bf16x2(cs[2 * kc + 1][0], cs[2 * kc + 1][1]);
            pa[3] = pack_bf16x2(cs[2 * kc + 1][2], cs[2 * kc + 1][3]);
            #pragma unroll
            for (int ep = 0; ep < 8; ep++) {
                uint32_t vb4[4];
                uint32_t offV = (uint32_t)((kc * 16 + vtrow) * 272 + (ep * 16 + vncol) * 2);
                LDSM_X4_T(vb4, vh_b + offV);
                MMA_BF16(o[2 * ep],     pa, &vb4[0]);
                MMA_BF16(o[2 * ep + 1], pa, &vb4[2]);
            }
        }
        buf ^= 1;
    }

    const int b_ = bh >> 3;
    float inv0 = 1.0f / lrow[0], inv1 = 1.0f / lrow[1];
    {
        int sp0 = h * 128 + (sg0 >> 3), fp0 = (sg0 & 7) << 7;
        int sp1 = h * 128 + (sg1 >> 3), fp1 = (sg1 & 7) << 7;
        float* d0 = g_att + ((size_t)b_ * 1024 + sp0) * 1024 + fp0;
        float* d1 = g_att + ((size_t)b_ * 1024 + sp1) * 1024 + fp1;
        #pragma unroll
        for (int nt = 0; nt < 16; nt++) {
            int e = nt * 8 + 2 * tg;
            *(float2*)(d0 + e) = make_float2(o[nt][0] * inv0, o[nt][1] * inv0);
            *(float2*)(d1 + e) = make_float2(o[nt][2] * inv1, o[nt][3] * inv1);
        }
    }
}

// ---------------- fused MLP + residual + LayerNorm (R13-proven) ----------------
__global__ __launch_bounds__(256) void mlp_ln_kernel(const float* __restrict__ X,
                                                     const float* __restrict__ Wm,
                                                     const float* __restrict__ gamma,
                                                     const float* __restrict__ beta,
                                                     float* __restrict__ out)
{
    __shared__ float At[32][32];
    __shared__ float Wt[32][128];
    const int m0 = blockIdx.x * 32;
    const int tid = threadIdx.x;
    const int tx = tid & 15, ty = tid >> 4;

    float acc[2][8] = {};

    for (int k0 = 0; k0 < 1024; k0 += 32) {
        __syncthreads();
        {
            int row = tid >> 3;
            int col = (tid & 7) << 2;
            *(float4*)(&At[row][col]) = *(const float4*)(g_att + (size_t)(m0 + row) * 1024 + k0 + col);
        }
        #pragma unroll
        for (int i = 0; i < 4; i++) {
            int f = tid + i * 256;
            int row = f >> 5;
            int col = (f & 31) << 2;
            *(float4*)(&Wt[row][col]) = *(const float4*)(Wm + (size_t)(k0 + row) * 128 + col);
        }
        __syncthreads();

        #pragma unroll
        for (int k4 = 0; k4 < 8; k4++) {
            float4 a[2];
            #pragma unroll
            for (int i = 0; i < 2; i++) a[i] = *(float4*)&At[ty * 2 + i][k4 * 4];
            float ws[4][8];
            #pragma unroll
            for (int kk = 0; kk < 4; kk++) {
                float4 u = *(float4*)&Wt[k4 * 4 + kk][tx * 8];
                float4 v = *(float4*)&Wt[k4 * 4 + kk][tx * 8 + 4];
                ws[kk][0] = u.x; ws[kk][1] = u.y; ws[kk][2] = u.z; ws[kk][3] = u.w;
                ws[kk][4] = v.x; ws[kk][5] = v.y; ws[kk][6] = v.z; ws[kk][7] = v.w;
            }
            #pragma unroll
            for (int i = 0; i < 2; i++)
                #pragma unroll
                for (int j = 0; j < 8; j++)
                    acc[i][j] += a[i].x * ws[0][j] + a[i].y * ws[1][j] + a[i].z * ws[2][j] + a[i].w * ws[3][j];
        }
    }

    float gj[8], bj[8];
    #pragma unroll
    for (int j = 0; j < 8; j++) { gj[j] = gamma[tx * 8 + j]; bj[j] = beta[tx * 8 + j]; }

    #pragma unroll
    for (int i = 0; i < 2; i++) {
        int r = m0 + ty * 2 + i;
        float y[8];
        float s = 0.f;
        #pragma unroll
        for (int j = 0; j < 8; j++) {
            y[j] = acc[i][j] + X[(size_t)r * 128 + tx * 8 + j];
            s += y[j];
        }
        #pragma unroll
        for (int off = 8; off; off >>= 1) s += __shfl_xor_sync(0xffffffffu, s, off);
        float mu = s * (1.0f / 128.0f);
        float vs = 0.f;
        #pragma unroll
        for (int j = 0; j < 8; j++) { float d = y[j] - mu; vs += d * d; }
        #pragma unroll
        for (int off = 8; off; off >>= 1) vs += __shfl_xor_sync(0xffffffffu, vs, off);
        float inv = rsqrtf(vs * (1.0f / 128.0f) + 1e-5f);
        #pragma unroll
        for (int j = 0; j < 8; j++)
            out[(size_t)r * 128 + tx * 8 + j] = (y[j] - mu) * inv * gj[j] + bj[j];
    }
}

// ---------------- launch ----------------
extern "C" void kernel_launch(void* const* d_in, const int* in_sizes, int n_in,
                              void* d_out, int out_size)
{
    const float* x     = (const float*)d_in[0];
    const float* memp  = (const float*)d_in[1];
    const float* u1    = (const float*)d_in[3];
    const float* u2    = (const float*)d_in[4];
    const float* w_q   = (const float*)d_in[5];
    const float* w_kv  = (const float*)d_in[6];
    const float* w_r   = (const float*)d_in[7];
    const float* w_mlp = (const float*)d_in[8];
    const float* ln_g  = (const float*)d_in[9];
    const float* ln_b  = (const float*)d_in[10];
    float* out = (float*)d_out;

    const int proj_smem  = (64 * 136 * 2 + 128 * 72 * 2) * 2;                      // 71,680 B
    const int ggemm_smem = (128 * 136 + 64 * 136 * 2) * 2;                         // 69,632 B
    const int attn_smem  = (128 * 136 + 2 * 64 * 136 * 3 + 2 * 128 * 80) * 2
                         + 2 * 128 * 4;                                            // 181,248 B
    cudaFuncSetAttribute(proj_mma_kernel<0>, cudaFuncAttributeMaxDynamicSharedMemorySize, proj_smem);
    cudaFuncSetAttribute(proj_mma_kernel<1>, cudaFuncAttributeMaxDynamicSharedMemorySize, proj_smem);
    cudaFuncSetAttribute(proj_mma_kernel<2>, cudaFuncAttributeMaxDynamicSharedMemorySize, proj_smem);
    cudaFuncSetAttribute(ggemm_mma_kernel, cudaFuncAttributeMaxDynamicSharedMemorySize, ggemm_smem);
    cudaFuncSetAttribute(attn_kernel,      cudaFuncAttributeMaxDynamicSharedMemorySize, attn_smem);

    pos_kernel<<<1024, 256>>>();
    proj_mma_kernel<0><<<dim3(16, 64), 256, proj_smem>>>(x, nullptr, w_q, 1024);
    proj_mma_kernel<1><<<dim3(32, 128), 256, proj_smem>>>(x, memp, w_kv, 2048);
    proj_mma_kernel<2><<<dim3(16, 32), 256, proj_smem>>>(nullptr, nullptr, w_r, 1024);
    udot_kernel<<<8192, 256>>>(u1, 0, NB * NH * TOT);
    udot_kernel<<<2048, 256>>>(u2, 1, NH * TOT);
    ggemm_mma_kernel<<<dim3(32, 8, 32), 256, ggemm_smem>>>();
    attn_kernel<<<dim3(8, 32), 256, attn_smem>>>();
    mlp_ln_kernel<<<128, 256>>>(x, w_mlp, ln_g, ln_b, out);
}

// round 17
// speedup vs baseline: 1.2197x; 1.0824x over previous
#include <cuda_runtime.h>
#include <cuda_bf16.h>
#include <math.h>
#include <stdint.h>

#define NB 4
#define NH 8
#define SEGL 1024
#define TOT 2048
#define DD 128

// ---------------- scratch (device globals; no allocations) ----------------
__device__ float g_pos[TOT*DD];           // sinusoid table
__device__ __nv_bfloat16 g_qh[NB*NH*SEGL*DD];
__device__ __nv_bfloat16 g_kh[NB*NH*TOT*DD];
__device__ __nv_bfloat16 g_kl[NB*NH*TOT*DD];   // used only by udot (exact u1.k bias)
__device__ __nv_bfloat16 g_vh[NB*NH*TOT*DD];   // V single bf16 plane
__device__ __nv_bfloat16 g_rh[NH*TOT*DD];
__device__ __nv_bfloat16 g_rl[NH*TOT*DD];
__device__ float g_u1k[NB*NH*TOT];
__device__ float g_u2r[NH*TOT];
__device__ float g_att[NB*SEGL*NH*DD];
__device__ __nv_bfloat16 g_G[(size_t)NB*NH*SEGL*TOT + 4096]; // +pad for aligned over-fetch

// ---------------- helpers ----------------
__device__ __forceinline__ uint32_t smem_u32(const void* p) {
    uint32_t a;
    asm("{ .reg .u64 t; cvta.to.shared.u64 t, %1; cvt.u32.u64 %0, t; }" : "=r"(a) : "l"(p));
    return a;
}
__device__ __forceinline__ uint32_t pack_bf16x2(float lo, float hi) {
    uint32_t d; asm("cvt.rn.bf16x2.f32 %0, %1, %2;" : "=r"(d) : "f"(hi), "f"(lo)); return d;
}
__device__ __forceinline__ void cp16(uint32_t dst, const void* src) {
    asm volatile("cp.async.cg.shared.global [%0], [%1], 16;" :: "r"(dst), "l"(src) : "memory");
}
#define CP_COMMIT() asm volatile("cp.async.commit_group;" ::: "memory")
#define CP_WAIT(n)  asm volatile("cp.async.wait_group %0;" :: "n"(n) : "memory")

#define LDSM_X4(r, addr) \
    asm volatile("ldmatrix.sync.aligned.m8n8.x4.shared.b16 {%0,%1,%2,%3}, [%4];" \
        : "=r"((r)[0]), "=r"((r)[1]), "=r"((r)[2]), "=r"((r)[3]) : "r"(addr))
#define LDSM_X4_T(r, addr) \
    asm volatile("ldmatrix.sync.aligned.m8n8.x4.trans.shared.b16 {%0,%1,%2,%3}, [%4];" \
        : "=r"((r)[0]), "=r"((r)[1]), "=r"((r)[2]), "=r"((r)[3]) : "r"(addr))
#define MMA_BF16(c, a, b) \
    asm volatile("mma.sync.aligned.m16n8k16.row.col.f32.bf16.bf16.f32 " \
        "{%0,%1,%2,%3}, {%4,%5,%6,%7}, {%8,%9}, {%0,%1,%2,%3};" \
        : "+f"((c)[0]), "+f"((c)[1]), "+f"((c)[2]), "+f"((c)[3]) \
        : "r"((a)[0]), "r"((a)[1]), "r"((a)[2]), "r"((a)[3]), "r"((b)[0]), "r"((b)[1]))

__device__ __forceinline__ void split4_bf16(float4 v, ushort4& hv, ushort4& lv) {
    __nv_bfloat16 b;
    b = __float2bfloat16(v.x); hv.x = __bfloat16_as_ushort(b);
    lv.x = __bfloat16_as_ushort(__float2bfloat16(v.x - __bfloat162float(b)));
    b = __float2bfloat16(v.y); hv.y = __bfloat16_as_ushort(b);
    lv.y = __bfloat16_as_ushort(__float2bfloat16(v.y - __bfloat162float(b)));
    b = __float2bfloat16(v.z); hv.z = __bfloat16_as_ushort(b);
    lv.z = __bfloat16_as_ushort(__float2bfloat16(v.z - __bfloat162float(b)));
    b = __float2bfloat16(v.w); hv.w = __bfloat16_as_ushort(b);
    lv.w = __bfloat16_as_ushort(__float2bfloat16(v.w - __bfloat162float(b)));
}
__device__ __forceinline__ void split2_bf16(float a, float b, ushort2& hv, ushort2& lv) {
    __nv_bfloat16 t;
    t = __float2bfloat16(a); hv.x = __bfloat16_as_ushort(t);
    lv.x = __bfloat16_as_ushort(__float2bfloat16(a - __bfloat162float(t)));
    t = __float2bfloat16(b); hv.y = __bfloat16_as_ushort(t);
    lv.y = __bfloat16_as_ushort(__float2bfloat16(b - __bfloat162float(t)));
}

// ---------------- sinusoid position table ----------------
__global__ __launch_bounds__(256) void pos_kernel()
{
    int idx = blockIdx.x * 256 + threadIdx.x;
    int m = idx >> 7, e = idx & 127;
    float pp = (float)(2047 - m);
    float ang = pp / powf(10000.0f, (float)(2 * e) * (1.0f / 128.0f));
    g_pos[idx] = ((e & 1) == 0) ? sinf(ang) : cosf(ang);
}

// ---------------- projection GEMMs: 64m x 64n tiles (R13-proven) ----------------
template<int MODE>
__global__ __launch_bounds__(256, 3) void proj_mma_kernel(const float* __restrict__ X,
                                                          const float* __restrict__ MEMI,
                                                          const float* __restrict__ W, int N)
{
    extern __shared__ __align__(16) unsigned short sm16[];
    unsigned short* Ah = sm16;              // 64*136
    unsigned short* Al = Ah + 64 * 136;
    unsigned short* Bh = Al + 64 * 136;     // 128*72 ([k][n])
    unsigned short* Bl = Bh + 128 * 72;

    const int m0 = blockIdx.y * 64;
    const int n0 = blockIdx.x * 64;
    const int tid = threadIdx.x, wid = tid >> 5, lane = tid & 31;

    #pragma unroll
    for (int i = 0; i < 8; i++) {
        int f = tid + i * 256;
        int row = f >> 5, col = (f & 31) << 2;
        int m = m0 + row;
        float4 a;
        if (MODE == 0) {
            a = *(const float4*)(X + (size_t)m * 128 + col);
        } else if (MODE == 1) {
            int bb = m >> 11, sp = m & 2047;
            const float* src = (sp < 1024) ? (MEMI + ((size_t)bb * 1024 + sp) * 128)
                                           : (X    + ((size_t)bb * 1024 + sp - 1024) * 128);
            a = *(const float4*)(src + col);
        } else {
            a = *(const float4*)(g_pos + (size_t)m * 128 + col);
        }
        ushort4 hv, lv;
        split4_bf16(a, hv, lv);
        *(ushort4*)(Ah + row * 136 + col) = hv;
        *(ushort4*)(Al + row * 136 + col) = lv;
    }
    #pragma unroll
    for (int i = 0; i < 8; i++) {
        int f = tid + i * 256;
        int row = f >> 4, col = (f & 15) << 2;
        float4 w = *(const float4*)(W + (size_t)row * N + n0 + col);
        ushort4 hv, lv;
        split4_bf16(w, hv, lv);
        *(ushort4*)(Bh + row * 72 + col) = hv;
        *(ushort4*)(Bl + row * 72 + col) = lv;
    }
    __syncthreads();

    const int wm = (wid >> 1) * 16;
    const int wn = (wid & 1) * 32;
    const int arow = (lane & 7) + ((lane >> 3) & 1) * 8;
    const int akoff = (lane >> 4) * 16;
    const int vtrow = ((lane >> 3) & 1) * 8 + (lane & 7);
    const int vncol = ((lane >> 4) & 1) * 8;

    const uint32_t ah_b = smem_u32(Ah), al_b = smem_u32(Al);
    const uint32_t bh_b = smem_u32(Bh), bl_b = smem_u32(Bl);

    float cs[4][4];
    #pragma unroll
    for (int nt = 0; nt < 4; nt++)
        #pragma unroll
        for (int e = 0; e < 4; e++) cs[nt][e] = 0.f;

    #pragma unroll
    for (int ks = 0; ks < 8; ks++) {
        uint32_t ah[4], al4[4];
        uint32_t offA = (uint32_t)((wm + arow) * 272 + ks * 32 + akoff);
        LDSM_X4(ah, ah_b + offA);
        LDSM_X4(al4, al_b + offA);
        #pragma unroll
        for (int np = 0; np < 2; np++) {
            uint32_t bh4[4], bl4[4];
            uint32_t offB = (uint32_t)((ks * 16 + vtrow) * 144 + (wn + np * 16 + vncol) * 2);
            LDSM_X4_T(bh4, bh_b + offB);
            LDSM_X4_T(bl4, bl_b + offB);
            MMA_BF16(cs[2 * np],     ah,  &bh4[0]);
            MMA_BF16(cs[2 * np],     ah,  &bl4[0]);
            MMA_BF16(cs[2 * np],     al4, &bh4[0]);
            MMA_BF16(cs[2 * np + 1], ah,  &bh4[2]);
            MMA_BF16(cs[2 * np + 1], ah,  &bl4[2]);
            MMA_BF16(cs[2 * np + 1], al4, &bh4[2]);
        }
    }

    const int gp = lane >> 2, tg = lane & 3;
    #pragma unroll
    for (int half = 0; half < 2; half++) {
        int m = m0 + wm + gp + 8 * half;
        #pragma unroll
        for (int nt = 0; nt < 4; nt++) {
            int col = wn + nt * 8 + 2 * tg;
            int fp = n0 + col;
            float v0 = cs[nt][2 * half], v1 = cs[nt][2 * half + 1];
            if (MODE == 0) {
                int b_ = m >> 10, sp = m & 1023;
                int h = sp >> 7;
                int s = ((sp & 127) << 3) + (fp >> 7);
                int e = fp & 127;
                size_t off = ((((size_t)b_ * 8 + h) * 1024 + s) << 7) + e;
                ushort2 hv;
                hv.x = __bfloat16_as_ushort(__float2bfloat16(v0));
                hv.y = __bfloat16_as_ushort(__float2bfloat16(v1));
                *(ushort2*)(g_qh + off) = hv;
            } else if (MODE == 1) {
                int bb = m >> 11, sp = m & 2047;
                int cc = bb * 2 + (sp >> 10);
                int h = (sp & 1023) >> 7;
                int t = ((sp & 127) << 4) + (fp >> 7);
                int e = fp & 127;
                if (cc < 4) {
                    size_t off = ((((size_t)cc * 8 + h) * 2048 + t) << 7) + e;
                    ushort2 hv, lv;
                    split2_bf16(v0, v1, hv, lv);
                    *(ushort2*)(g_kh + off) = hv;
                    *(ushort2*)(g_kl + off) = lv;
                } else {
                    size_t off = ((((size_t)(cc - 4) * 8 + h) * 2048 + t) << 7) + e;
                    ushort2 hv;
                    hv.x = __bfloat16_as_ushort(__float2bfloat16(v0));
                    hv.y = __bfloat16_as_ushort(__float2bfloat16(v1));
                    *(ushort2*)(g_vh + off) = hv;
                }
            } else {
                int h = m >> 8;
                int t = ((m & 255) << 3) + (fp >> 7);
                int e = fp & 127;
                size_t off = (((size_t)h * 2048 + t) << 7) + e;
                ushort2 hv, lv;
                split2_bf16(v0, v1, hv, lv);
                *(ushort2*)(g_rh + off) = hv;
                *(ushort2*)(g_rl + off) = lv;
            }
        }
    }
}

// ---------------- u1·k and u2·r from bf16 hi/lo planes ----------------
__global__ __launch_bounds__(256) void udot_kernel(const float* __restrict__ U, int which, int nrows)
{
    int row = blockIdx.x * 8 + (threadIdx.x >> 5);
    int lane = threadIdx.x & 31;
    if (row >= nrows) return;
    const __nv_bfloat16* Mh = which ? g_rh : g_kh;
    const __nv_bfloat16* Ml = which ? g_rl : g_kl;
    float* Out = which ? g_u2r : g_u1k;
    int h = (row >> 11) & 7;
    float4 u = *(const float4*)(U + h * 128 + lane * 4);
    ushort4 mh = *(const ushort4*)(Mh + (size_t)row * 128 + lane * 4);
    ushort4 ml = *(const ushort4*)(Ml + (size_t)row * 128 + lane * 4);
    float m0 = __bfloat162float(__ushort_as_bfloat16(mh.x)) + __bfloat162float(__ushort_as_bfloat16(ml.x));
    float m1 = __bfloat162float(__ushort_as_bfloat16(mh.y)) + __bfloat162float(__ushort_as_bfloat16(ml.y));
    float m2 = __bfloat162float(__ushort_as_bfloat16(mh.z)) + __bfloat162float(__ushort_as_bfloat16(ml.z));
    float m3 = __bfloat162float(__ushort_as_bfloat16(mh.w)) + __bfloat162float(__ushort_as_bfloat16(ml.w));
    float s = u.x * m0 + u.y * m1 + u.z * m2 + u.w * m3;
    #pragma unroll
    for (int o = 16; o; o >>= 1) s += __shfl_xor_sync(0xffffffffu, s, o);
    if (lane == 0) Out[row] = s;
}

// ---------------- banded G = qh.(rh+rl) via bf16 mma.sync (2-term, R15-proven) ----------------
__global__ __launch_bounds__(256, 2) void ggemm_mma_kernel()
{
    extern __shared__ __align__(16) unsigned short sm16[];
    unsigned short* Qh = sm16;              // 128*136
    unsigned short* Rh = Qh + 128 * 136;    // 64*136
    unsigned short* Rl = Rh + 64 * 136;

    const int rt = blockIdx.x, st = blockIdx.y, bh = blockIdx.z;
    if (rt < 14 - 2 * st) return;
    const int h = bh & 7;
    const int s0 = st * 128, r0 = rt * 64;
    const int tid = threadIdx.x, wid = tid >> 5, lane = tid & 31;

    const unsigned short* qh = (const unsigned short*)g_qh + ((size_t)bh * 1024 + s0) * 128;
    #pragma unroll
    for (int i = 0; i < 8; i++) {
        int f = tid + i * 256;
        int row = f >> 4, c8 = (f & 15) << 3;
        *(uint4*)(Qh + row * 136 + c8) = *(const uint4*)(qh + (size_t)row * 128 + c8);
    }
    const unsigned short* rh = (const unsigned short*)g_rh + ((size_t)h * 2048 + r0) * 128;
    const unsigned short* rl = (const unsigned short*)g_rl + ((size_t)h * 2048 + r0) * 128;
    #pragma unroll
    for (int i = 0; i < 4; i++) {
        int f = tid + i * 256;
        int row = f >> 4, c8 = (f & 15) << 3;
        *(uint4*)(Rh + row * 136 + c8) = *(const uint4*)(rh + (size_t)row * 128 + c8);
        *(uint4*)(Rl + row * 136 + c8) = *(const uint4*)(rl + (size_t)row * 128 + c8);
    }
    __syncthreads();

    const int wm = (wid >> 1) * 32;
    const int wn = (wid & 1) * 32;

    float c[2][4][4];
    #pragma unroll
    for (int mt = 0; mt < 2; mt++)
        #pragma unroll
        for (int nt = 0; nt < 4; nt++)
            #pragma unroll
            for (int e = 0; e < 4; e++) c[mt][nt][e] = 0.f;

    const int arow = (lane & 7) + ((lane >> 3) & 1) * 8;
    const int akoff = (lane >> 4) * 16;
    const int brow = lane & 7;
    const int bkoff = ((lane >> 3) & 1) * 16;

    const uint32_t qh_b = smem_u32(Qh);
    const uint32_t rh_b = smem_u32(Rh), rl_b = smem_u32(Rl);

    #pragma unroll
    for (int ks = 0; ks < 8; ks++) {
        uint32_t ah[2][4];
        #pragma unroll
        for (int mt = 0; mt < 2; mt++) {
            uint32_t off = (uint32_t)((wm + mt * 16 + arow) * 272 + ks * 32 + akoff);
            LDSM_X4(ah[mt], qh_b + off);
        }
        uint32_t bhf[4][2], blf[4][2];
        #pragma unroll
        for (int nt = 0; nt < 4; nt++) {
            uint32_t off = (uint32_t)((wn + nt * 8 + brow) * 272 + ks * 32 + bkoff);
            asm volatile("ldmatrix.sync.aligned.m8n8.x2.shared.b16 {%0,%1}, [%2];"
                : "=r"(bhf[nt][0]), "=r"(bhf[nt][1]) : "r"(rh_b + off));
            asm volatile("ldmatrix.sync.aligned.m8n8.x2.shared.b16 {%0,%1}, [%2];"
                : "=r"(blf[nt][0]), "=r"(blf[nt][1]) : "r"(rl_b + off));
        }
        #pragma unroll
        for (int mt = 0; mt < 2; mt++)
            #pragma unroll
            for (int nt = 0; nt < 4; nt++) {
                MMA_BF16(c[mt][nt], ah[mt], bhf[nt]);
                MMA_BF16(c[mt][nt], ah[mt], blf[nt]);
            }
    }

    const int gp = lane >> 2, tg = lane & 3;
    __nv_bfloat16* Gb = g_G + (size_t)bh * (1024 * 2048);
    #pragma unroll
    for (int mt = 0; mt < 2; mt++) {
        int mrow = s0 + wm + mt * 16 + gp;
        #pragma unroll
        for (int nt = 0; nt < 4; nt++) {
            int n = r0 + wn + nt * 8 + 2 * tg;
            *(uint32_t*)(Gb + (size_t)mrow * 2048 + n)       = pack_bf16x2(c[mt][nt][0], c[mt][nt][1]);
            *(uint32_t*)(Gb + (size_t)(mrow + 8) * 2048 + n) = pack_bf16x2(c[mt][nt][2], c[mt][nt][3]);
        }
    }
}

// ---------------- flash attention: 8 warps, qh.kh QK (1-term), cp.async pipeline ----------------
__global__ __launch_bounds__(256, 1) void attn_kernel()
{
    extern __shared__ __align__(16) char smraw[];
    unsigned short* Qh  = (unsigned short*)smraw;     // 128*136
    unsigned short* Kh0 = Qh + 128 * 136;             // 2 bufs x 64*136
    unsigned short* Vh0 = Kh0 + 2 * 64 * 136;
    unsigned short* Gs0 = Vh0 + 2 * 64 * 136;         // 2 bufs x 128*80
    float* biasF = (float*)(Gs0 + 2 * 128 * 80);      // 2 bufs x 128 floats (u1k|u2r)

    const int st = 7 - blockIdx.x;                    // heavy-first
    const int bh = blockIdx.y, h = bh & 7;
    const int s0 = st * 128;
    const int tid = threadIdx.x;
    const int wid = tid >> 5, lane = tid & 31;
    const int wm = wid * 16;
    const int gp = lane >> 2, tg = lane & 3;
    const int arow = (lane & 7) + ((lane >> 3) & 1) * 8;
    const int akoff = (lane >> 4) * 16;
    const int b4row = ((lane >> 4) & 1) * 8 + (lane & 7);
    const int b4koff = ((lane >> 3) & 1) * 16;
    const int vtrow = ((lane >> 3) & 1) * 8 + (lane & 7);
    const int vncol = ((lane >> 4) & 1) * 8;

    const unsigned short* qhp = (const unsigned short*)g_qh + ((size_t)bh * 1024 + s0) * 128;
    const unsigned short* khp = (const unsigned short*)g_kh + (size_t)bh * (2048 * 128);
    const unsigned short* vhp = (const unsigned short*)g_vh + (size_t)bh * (2048 * 128);
    const unsigned short* Gbh = (const unsigned short*)g_G + (size_t)bh * (1024 * 2048);

    #pragma unroll
    for (int i = 0; i < 8; i++) {
        int f = tid + i * 256;
        int row = f >> 4, c8 = (f & 15) << 3;
        *(uint4*)(Qh + row * 136 + c8) = *(const uint4*)(qhp + (size_t)row * 128 + c8);
    }

    const uint32_t qh_b = smem_u32(Qh);
    const uint32_t khBase = smem_u32(Kh0), vhBase = smem_u32(Vh0);
    const uint32_t gsBase = smem_u32(Gs0), biasBase = smem_u32(biasF);

    auto stage = [&](int b, int tt) {
        const int t0 = tt * 64;
        const uint32_t kh = khBase + b * 17408;
        const uint32_t vh = vhBase + b * 17408;
        const uint32_t gs = gsBase + b * 20480;
        const uint32_t bb = biasBase + b * 512;
        #pragma unroll
        for (int i = 0; i < 8; i++) {            // K hi + V: 2 x 1024 chunks
            int idx = tid + i * 256;
            int p = idx >> 10;
            int rc = idx & 1023;
            int row = rc >> 4, ch = rc & 15;
            uint32_t dst = (p == 0 ? kh : vh) + (uint32_t)(row * 272 + ch * 16);
            const unsigned short* src = (p == 0 ? khp : vhp)
                                      + (size_t)(t0 + row) * 128 + ch * 8;
            cp16(dst, src);
        }
        const int relbase = t0 - s0 + 1023;
        #pragma unroll
        for (int i = 0; i < 5; i++) {            // G band: 1152 chunks
            int idx = tid + i * 256;
            if (idx < 1152) {
                int row = idx / 9, ch = idx - row * 9;
                int start = (relbase - row) & ~7;
                cp16(gs + (uint32_t)(row * 160 + ch * 16),
                     Gbh + (size_t)(s0 + row) * 2048 + start + ch * 8);
            }
        }
        if (tid < 32) {
            int arr = tid >> 4, c = tid & 15;
            const float* src = arr ? (g_u2r + (size_t)h * 2048 + t0 + c * 4)
                                   : (g_u1k + (size_t)bh * 2048 + t0 + c * 4);
            cp16(bb + (uint32_t)(arr * 256 + c * 16), src);
        }
    };

    float o[16][4];
    #pragma unroll
    for (int nt = 0; nt < 16; nt++)
        #pragma unroll
        for (int e = 0; e < 4; e++) o[nt][e] = 0.f;

    float mrow[2], lrow[2];
    mrow[0] = mrow[1] = -1e30f;
    lrow[0] = lrow[1] = 0.f;

    const float scale = 0.08838834764831843f; // 1/sqrt(128)
    const int r0 = wm + gp, r1 = r0 + 8;
    const int sg0 = s0 + r0, sg1 = s0 + r1;

    const int ntiles = 2 * st + 18;
    stage(0, 0);
    CP_COMMIT();
    int buf = 0;

    for (int tt = 0; tt < ntiles; tt++) {
        __syncthreads();
        if (tt + 1 < ntiles) {
            stage(buf ^ 1, tt + 1);
            CP_COMMIT();
            CP_WAIT(1);
        } else {
            CP_WAIT(0);
        }
        __syncthreads();

        const int t0 = tt * 64;
        const int relbase = t0 - s0 + 1023;
        const uint32_t kh_b = khBase + buf * 17408;
        const uint32_t vh_b = vhBase + buf * 17408;
        const unsigned short* GsB = Gs0 + buf * 10240;
        const float* bA = biasF + buf * 128;
        const int off0 = (relbase - r0) & 7;
        const int off1 = (relbase - r1) & 7;

        // ---- QK (1-term: qh.kh) ----
        float cs[8][4];
        #pragma unroll
        for (int nt = 0; nt < 8; nt++)
            #pragma unroll
            for (int e = 0; e < 4; e++) cs[nt][e] = 0.f;

        #pragma unroll
        for (int ks = 0; ks < 8; ks++) {
            uint32_t ah[4];
            uint32_t offA = (uint32_t)((wm + arow) * 272 + ks * 32 + akoff);
            LDSM_X4(ah, qh_b + offA);
            #pragma unroll
            for (int np = 0; np < 4; np++) {
                uint32_t bh4[4];
                uint32_t offB = (uint32_t)((np * 16 + b4row) * 272 + ks * 32 + b4koff);
                LDSM_X4(bh4, kh_b + offB);
                MMA_BF16(cs[2 * np],     ah, &bh4[0]);
                MMA_BF16(cs[2 * np + 1], ah, &bh4[2]);
            }
        }

        float mx0 = -1e30f, mx1 = -1e30f;
        #pragma unroll
        for (int nt = 0; nt < 8; nt++) {
            int col = nt * 8 + 2 * tg;
            int tgl = t0 + col;
            float b0 = bA[col] + bA[64 + col];
            float b1 = bA[col + 1] + bA[64 + col + 1];
            float g00 = __bfloat162float(*(const __nv_bfloat16*)(GsB + r0 * 80 + off0 + col));
            float g01 = __bfloat162float(*(const __nv_bfloat16*)(GsB + r0 * 80 + off0 + col + 1));
            float g10 = __bfloat162float(*(const __nv_bfloat16*)(GsB + r1 * 80 + off1 + col));
            float g11 = __bfloat162float(*(const __nv_bfloat16*)(GsB + r1 * 80 + off1 + col + 1));
            float v00 = (cs[nt][0] + g00 + b0) * scale;
            float v01 = (cs[nt][1] + g01 + b1) * scale;
            float v10 = (cs[nt][2] + g10 + b0) * scale;
            float v11 = (cs[nt][3] + g11 + b1) * scale;
            v00 = (tgl     - sg0 <= 1024) ? v00 : -1e30f;
            v01 = (tgl + 1 - sg0 <= 1024) ? v01 : -1e30f;
            v10 = (tgl     - sg1 <= 1024) ? v10 : -1e30f;
            v11 = (tgl + 1 - sg1 <= 1024) ? v11 : -1e30f;
            cs[nt][0] = v00; cs[nt][1] = v01; cs[nt][2] = v10; cs[nt][3] = v11;
            mx0 = fmaxf(mx0, fmaxf(v00, v01));
            mx1 = fmaxf(mx1, fmaxf(v10, v11));
        }
        mx0 = fmaxf(mx0, __shfl_xor_sync(0xffffffffu, mx0, 1));
        mx0 = fmaxf(mx0, __shfl_xor_sync(0xffffffffu, mx0, 2));
        mx1 = fmaxf(mx1, __shfl_xor_sync(0xffffffffu, mx1, 1));
        mx1 = fmaxf(mx1, __shfl_xor_sync(0xffffffffu, mx1, 2));

        float mn0 = fmaxf(mrow[0], mx0), mn1 = fmaxf(mrow[1], mx1);
        float al0 = __expf(mrow[0] - mn0), al1 = __expf(mrow[1] - mn1);
        float rs0 = 0.f, rs1 = 0.f;
        #pragma unroll
        for (int nt = 0; nt < 8; nt++) {
            float p00 = __expf(cs[nt][0] - mn0), p01 = __expf(cs[nt][1] - mn0);
            float p10 = __expf(cs[nt][2] - mn1), p11 = __expf(cs[nt][3] - mn1);
            rs0 += p00 + p01; rs1 += p10 + p11;
            cs[nt][0] = p00; cs[nt][1] = p01; cs[nt][2] = p10; cs[nt][3] = p11;
        }
        rs0 += __shfl_xor_sync(0xffffffffu, rs0, 1);
        rs0 += __shfl_xor_sync(0xffffffffu, rs0, 2);
        rs1 += __shfl_xor_sync(0xffffffffu, rs1, 1);
        rs1 += __shfl_xor_sync(0xffffffffu, rs1, 2);
        lrow[0] = lrow[0] * al0 + rs0; mrow[0] = mn0;
        lrow[1] = lrow[1] * al1 + rs1; mrow[1] = mn1;

        #pragma unroll
        for (int nt = 0; nt < 16; nt++) {
            o[nt][0] *= al0; o[nt][1] *= al0;
            o[nt][2] *= al1; o[nt][3] *= al1;
        }

        #pragma unroll
        for (int kc = 0; kc < 4; kc++) {
            uint32_t pa[4];
            pa[0] = pack_bf16x2(cs[2 * kc][0],     cs[2 * kc][1]);
            pa[1] = pack_bf16x2(cs[2 * kc][2],     cs[2 * kc][3]);
            pa[2] = pack_bf16x2(cs[2 * kc + 1][0], cs[2 * kc + 1][1]);
            pa[3] = pack_bf16x2(cs[2 * kc + 1][2], cs[2 * kc + 1][3]);
            #pragma unroll
            for (int ep = 0; ep < 8; ep++) {
                uint32_t vb4[4];
                uint32_t offV = (uint32_t)((kc * 16 + vtrow) * 272 + (ep * 16 + vncol) * 2);
                LDSM_X4_T(vb4, vh_b + offV);
                MMA_BF16(o[2 * ep],     pa, &vb4[0]);
                MMA_BF16(o[2 * ep + 1], pa, &vb4[2]);
            }
        }
        buf ^= 1;
    }

    const int b_ = bh >> 3;
    float inv0 = 1.0f / lrow[0], inv1 = 1.0f / lrow[1];
    {
        int sp0 = h * 128 + (sg0 >> 3), fp0 = (sg0 & 7) << 7;
        int sp1 = h * 128 + (sg1 >> 3), fp1 = (sg1 & 7) << 7;
        float* d0 = g_att + ((size_t)b_ * 1024 + sp0) * 1024 + fp0;
        float* d1 = g_att + ((size_t)b_ * 1024 + sp1) * 1024 + fp1;
        #pragma unroll
        for (int nt = 0; nt < 16; nt++) {
            int e = nt * 8 + 2 * tg;
            *(float2*)(d0 + e) = make_float2(o[nt][0] * inv0, o[nt][1] * inv0);
            *(float2*)(d1 + e) = make_float2(o[nt][2] * inv1, o[nt][3] * inv1);
        }
    }
}

// ---------------- fused MLP + residual + LayerNorm (R13-proven) ----------------
__global__ __launch_bounds__(256) void mlp_ln_kernel(const float* __restrict__ X,
                                                     const float* __restrict__ Wm,
                                                     const float* __restrict__ gamma,
                                                     const float* __restrict__ beta,
                                                     float* __restrict__ out)
{
    __shared__ float At[32][32];
    __shared__ float Wt[32][128];
    const int m0 = blockIdx.x * 32;
    const int tid = threadIdx.x;
    const int tx = tid & 15, ty = tid >> 4;

    float acc[2][8] = {};

    for (int k0 = 0; k0 < 1024; k0 += 32) {
        __syncthreads();
        {
            int row = tid >> 3;
            int col = (tid & 7) << 2;
            *(float4*)(&At[row][col]) = *(const float4*)(g_att + (size_t)(m0 + row) * 1024 + k0 + col);
        }
        #pragma unroll
        for (int i = 0; i < 4; i++) {
            int f = tid + i * 256;
            int row = f >> 5;
            int col = (f & 31) << 2;
            *(float4*)(&Wt[row][col]) = *(const float4*)(Wm + (size_t)(k0 + row) * 128 + col);
        }
        __syncthreads();

        #pragma unroll
        for (int k4 = 0; k4 < 8; k4++) {
            float4 a[2];
            #pragma unroll
            for (int i = 0; i < 2; i++) a[i] = *(float4*)&At[ty * 2 + i][k4 * 4];
            float ws[4][8];
            #pragma unroll
            for (int kk = 0; kk < 4; kk++) {
                float4 u = *(float4*)&Wt[k4 * 4 + kk][tx * 8];
                float4 v = *(float4*)&Wt[k4 * 4 + kk][tx * 8 + 4];
                ws[kk][0] = u.x; ws[kk][1] = u.y; ws[kk][2] = u.z; ws[kk][3] = u.w;
                ws[kk][4] = v.x; ws[kk][5] = v.y; ws[kk][6] = v.z; ws[kk][7] = v.w;
            }
            #pragma unroll
            for (int i = 0; i < 2; i++)
                #pragma unroll
                for (int j = 0; j < 8; j++)
                    acc[i][j] += a[i].x * ws[0][j] + a[i].y * ws[1][j] + a[i].z * ws[2][j] + a[i].w * ws[3][j];
        }
    }

    float gj[8], bj[8];
    #pragma unroll
    for (int j = 0; j < 8; j++) { gj[j] = gamma[tx * 8 + j]; bj[j] = beta[tx * 8 + j]; }

    #pragma unroll
    for (int i = 0; i < 2; i++) {
        int r = m0 + ty * 2 + i;
        float y[8];
        float s = 0.f;
        #pragma unroll
        for (int j = 0; j < 8; j++) {
            y[j] = acc[i][j] + X[(size_t)r * 128 + tx * 8 + j];
            s += y[j];
        }
        #pragma unroll
        for (int off = 8; off; off >>= 1) s += __shfl_xor_sync(0xffffffffu, s, off);
        float mu = s * (1.0f / 128.0f);
        float vs = 0.f;
        #pragma unroll
        for (int j = 0; j < 8; j++) { float d = y[j] - mu; vs += d * d; }
        #pragma unroll
        for (int off = 8; off; off >>= 1) vs += __shfl_xor_sync(0xffffffffu, vs, off);
        float inv = rsqrtf(vs * (1.0f / 128.0f) + 1e-5f);
        #pragma unroll
        for (int j = 0; j < 8; j++)
            out[(size_t)r * 128 + tx * 8 + j] = (y[j] - mu) * inv * gj[j] + bj[j];
    }
}

// ---------------- launch ----------------
extern "C" void kernel_launch(void* const* d_in, const int* in_sizes, int n_in,
                              void* d_out, int out_size)
{
    const float* x     = (const float*)d_in[0];
    const float* memp  = (const float*)d_in[1];
    const float* u1    = (const float*)d_in[3];
    const float* u2    = (const float*)d_in[4];
    const float* w_q   = (const float*)d_in[5];
    const float* w_kv  = (const float*)d_in[6];
    const float* w_r   = (const float*)d_in[7];
    const float* w_mlp = (const float*)d_in[8];
    const float* ln_g  = (const float*)d_in[9];
    const float* ln_b  = (const float*)d_in[10];
    float* out = (float*)d_out;

    const int proj_smem  = (64 * 136 * 2 + 128 * 72 * 2) * 2;                      // 71,680 B
    const int ggemm_smem = (128 * 136 + 64 * 136 * 2) * 2;                         // 69,632 B
    const int attn_smem  = (128 * 136 + 2 * 64 * 136 * 2 + 2 * 128 * 80) * 2
                         + 2 * 128 * 4;                                            // 146,432 B
    cudaFuncSetAttribute(proj_mma_kernel<0>, cudaFuncAttributeMaxDynamicSharedMemorySize, proj_smem);
    cudaFuncSetAttribute(proj_mma_kernel<1>, cudaFuncAttributeMaxDynamicSharedMemorySize, proj_smem);
    cudaFuncSetAttribute(proj_mma_kernel<2>, cudaFuncAttributeMaxDynamicSharedMemorySize, proj_smem);
    cudaFuncSetAttribute(ggemm_mma_kernel, cudaFuncAttributeMaxDynamicSharedMemorySize, ggemm_smem);
    cudaFuncSetAttribute(attn_kernel,      cudaFuncAttributeMaxDynamicSharedMemorySize, attn_smem);

    pos_kernel<<<1024, 256>>>();
    proj_mma_kernel<0><<<dim3(16, 64), 256, proj_smem>>>(x, nullptr, w_q, 1024);
    proj_mma_kernel<1><<<dim3(32, 128), 256, proj_smem>>>(x, memp, w_kv, 2048);
    proj_mma_kernel<2><<<dim3(16, 32), 256, proj_smem>>>(nullptr, nullptr, w_r, 1024);
    udot_kernel<<<8192, 256>>>(u1, 0, NB * NH * TOT);
    udot_kernel<<<2048, 256>>>(u2, 1, NH * TOT);
    ggemm_mma_kernel<<<dim3(32, 8, 32), 256, ggemm_smem>>>();
    attn_kernel<<<dim3(8, 32), 256, attn_smem>>>();
    mlp_ln_kernel<<<128, 256>>>(x, w_mlp, ln_g, ln_b, out);
}